// round 2
// baseline (speedup 1.0000x reference)
#include <cuda_runtime.h>
#include <math.h>

// ---------------------------------------------------------------------------
// DinoDecoderBlock: B=8, NQ=NK=1024, C=768, H=12, HD=64, HID=3072
// Round 2: fix mask dtype (harness materializes bool as int32; auto-detect
// int32 vs packed-u8 and decode to a u8 scratch mask). fp32 baseline otherwise.
// ---------------------------------------------------------------------------

#define Bb   8
#define NQ   1024
#define NK   1024
#define Cc   768
#define Hh   12
#define HD   64
#define HID  3072
#define MROWS (Bb*NQ)          // 8192
#define SCALE 0.125f

// ------------------------- scratch (no allocs allowed) ---------------------
__device__ float g_ln   [(size_t)MROWS*Cc];
__device__ float g_qkv  [(size_t)MROWS*3*Cc];
__device__ float g_scores[(size_t)Bb*Hh*NQ*NK];       // 402 MB
__device__ float g_attno[(size_t)MROWS*Cc];
__device__ float g_x1   [(size_t)MROWS*Cc];
__device__ float g_x2   [(size_t)MROWS*Cc];
__device__ float g_yln  [(size_t)MROWS*Cc];
__device__ float g_q    [(size_t)MROWS*Cc];
__device__ float g_k    [(size_t)MROWS*Cc];
__device__ float g_v    [(size_t)MROWS*Cc];
__device__ float g_h1   [(size_t)MROWS*HID];
__device__ unsigned char g_mask[(size_t)NQ*NK];
__device__ int g_mask_is_u8;

// --------------------------- mask detect/decode ----------------------------
// Single block: decide whether the mask buffer is int32 {0,1} per element or
// packed bytes. If any 32-bit word holds a value outside {0,1}, it's bytes.
__global__ void mask_detect(const unsigned int* __restrict__ m)
{
    __shared__ int flag;
    if (threadIdx.x == 0) flag = 0;
    __syncthreads();
    // scan 64K words; random u8 0/1 data gives a word >1 almost surely
    for (int i = threadIdx.x; i < 65536; i += blockDim.x)
        if (m[i] > 1u) flag = 1;
    __syncthreads();
    if (threadIdx.x == 0) g_mask_is_u8 = flag;
}

__global__ void mask_decode(const void* __restrict__ msrc)
{
    size_t i = (size_t)blockIdx.x * blockDim.x + threadIdx.x;
    if (i >= (size_t)NQ * NK) return;
    unsigned char v;
    if (g_mask_is_u8) v = ((const unsigned char*)msrc)[i] ? 1 : 0;
    else              v = ((const int*)msrc)[i] ? 1 : 0;
    g_mask[i] = v;
}

// ------------------------------ LayerNorm ----------------------------------
// one block (256 thr) per row of 768
__global__ void ln_kernel(const float* __restrict__ X, const float* __restrict__ g,
                          const float* __restrict__ b, float* __restrict__ O)
{
    int row = blockIdx.x;
    const float* x = X + (size_t)row * Cc;
    float*       o = O + (size_t)row * Cc;
    int t = threadIdx.x;
    float v0 = x[t], v1 = x[t + 256], v2 = x[t + 512];
    float s  = v0 + v1 + v2;
    float s2 = v0*v0 + v1*v1 + v2*v2;
    #pragma unroll
    for (int off = 16; off; off >>= 1) {
        s  += __shfl_xor_sync(0xffffffffu, s,  off);
        s2 += __shfl_xor_sync(0xffffffffu, s2, off);
    }
    __shared__ float shs[8], shs2[8];
    int w = t >> 5, l = t & 31;
    if (l == 0) { shs[w] = s; shs2[w] = s2; }
    __syncthreads();
    if (w == 0) {
        s  = (l < 8) ? shs[l]  : 0.f;
        s2 = (l < 8) ? shs2[l] : 0.f;
        #pragma unroll
        for (int off = 4; off; off >>= 1) {
            s  += __shfl_xor_sync(0xffffffffu, s,  off);
            s2 += __shfl_xor_sync(0xffffffffu, s2, off);
        }
        if (l == 0) { shs[0] = s; shs2[0] = s2; }
    }
    __syncthreads();
    float mean = shs[0] * (1.f / Cc);
    float var  = shs2[0] * (1.f / Cc) - mean * mean;
    float inv  = rsqrtf(var + 1e-5f);
    o[t]       = (v0 - mean) * inv * g[t]       + b[t];
    o[t + 256] = (v1 - mean) * inv * g[t + 256] + b[t + 256];
    o[t + 512] = (v2 - mean) * inv * g[t + 512] + b[t + 512];
}

// ------------------------------ GEMM (NT) ----------------------------------
// C[M,N] = A[M,K] @ W[N,K]^T  (+bias[n]) (gelu) (+res[M,N])
// M,N divisible by 64; K divisible by 16. 256 threads, 4x4 microtile.
__global__ void gemm_nt(const float* __restrict__ A, const float* __restrict__ W,
                        float* __restrict__ Cout, int M, int N, int K,
                        const float* __restrict__ bias,
                        const float* __restrict__ res, int gelu)
{
    __shared__ float As[16][68];
    __shared__ float Bs[16][68];
    int bx = blockIdx.x, by = blockIdx.y;
    int t  = threadIdx.x;
    int tx = t & 15, ty = t >> 4;
    const float* Ab = A + (size_t)(by * 64) * K;
    const float* Wb = W + (size_t)(bx * 64) * K;
    float acc[4][4] = {};
    int lrow = t >> 2;          // 0..63
    int lcol = (t & 3) * 4;     // 0,4,8,12
    for (int k0 = 0; k0 < K; k0 += 16) {
        float4 a4 = *(const float4*)(Ab + (size_t)lrow * K + k0 + lcol);
        As[lcol + 0][lrow] = a4.x; As[lcol + 1][lrow] = a4.y;
        As[lcol + 2][lrow] = a4.z; As[lcol + 3][lrow] = a4.w;
        float4 b4 = *(const float4*)(Wb + (size_t)lrow * K + k0 + lcol);
        Bs[lcol + 0][lrow] = b4.x; Bs[lcol + 1][lrow] = b4.y;
        Bs[lcol + 2][lrow] = b4.z; Bs[lcol + 3][lrow] = b4.w;
        __syncthreads();
        #pragma unroll
        for (int kk = 0; kk < 16; kk++) {
            float ra[4], rb[4];
            #pragma unroll
            for (int i = 0; i < 4; i++) ra[i] = As[kk][ty * 4 + i];
            #pragma unroll
            for (int j = 0; j < 4; j++) rb[j] = Bs[kk][tx * 4 + j];
            #pragma unroll
            for (int i = 0; i < 4; i++)
                #pragma unroll
                for (int j = 0; j < 4; j++)
                    acc[i][j] += ra[i] * rb[j];
        }
        __syncthreads();
    }
    #pragma unroll
    for (int i = 0; i < 4; i++) {
        int r = by * 64 + ty * 4 + i;
        #pragma unroll
        for (int j = 0; j < 4; j++) {
            int c = bx * 64 + tx * 4 + j;
            float v = acc[i][j];
            if (bias) v += bias[c];
            if (gelu) v = 0.5f * v * (1.0f + erff(v * 0.70710678118654752f));
            if (res)  v += res[(size_t)r * N + c];
            Cout[(size_t)r * N + c] = v;
        }
    }
}

// --------------------------- attention scores ------------------------------
// S[bh,n,m] = SCALE * sum_d Q[b, n, h, d] * K[b, m, h, d]
__global__ void attn_scores(const float* __restrict__ Q, const float* __restrict__ Kp,
                            float* __restrict__ S, size_t qBatch, size_t kBatch,
                            int qRow, int kRow)
{
    int bh = blockIdx.z;
    int b = bh / Hh, h = bh % Hh;
    const float* Qb = Q + (size_t)b * qBatch + h * HD;
    const float* Kb = Kp + (size_t)b * kBatch + h * HD;
    float* Sb = S + (size_t)bh * NQ * NK;
    __shared__ float Qs[64][65];
    __shared__ float Ks[64][65];
    int n0 = blockIdx.y * 64, m0 = blockIdx.x * 64;
    int t = threadIdx.x;
    #pragma unroll
    for (int i = 0; i < 4; i++) {
        int idx = t + i * 256;
        int r = idx >> 4;
        int c = (idx & 15) * 4;
        float4 q4 = *(const float4*)(Qb + (size_t)(n0 + r) * qRow + c);
        Qs[r][c] = q4.x; Qs[r][c+1] = q4.y; Qs[r][c+2] = q4.z; Qs[r][c+3] = q4.w;
        float4 k4 = *(const float4*)(Kb + (size_t)(m0 + r) * kRow + c);
        Ks[r][c] = k4.x; Ks[r][c+1] = k4.y; Ks[r][c+2] = k4.z; Ks[r][c+3] = k4.w;
    }
    __syncthreads();
    int tx = t & 15, ty = t >> 4;
    float acc[4][4] = {};
    #pragma unroll 8
    for (int kk = 0; kk < 64; kk++) {
        float ra[4], rb[4];
        #pragma unroll
        for (int i = 0; i < 4; i++) ra[i] = Qs[ty * 4 + i][kk];
        #pragma unroll
        for (int j = 0; j < 4; j++) rb[j] = Ks[tx * 4 + j][kk];
        #pragma unroll
        for (int i = 0; i < 4; i++)
            #pragma unroll
            for (int j = 0; j < 4; j++)
                acc[i][j] += ra[i] * rb[j];
    }
    #pragma unroll
    for (int i = 0; i < 4; i++)
        #pragma unroll
        for (int j = 0; j < 4; j++)
            Sb[(size_t)(n0 + ty * 4 + i) * NK + m0 + tx * 4 + j] = acc[i][j] * SCALE;
}

// ------------------------------- softmax -----------------------------------
// one block (256 thr) per row of NK=1024; optional decoded u8 mask[NQ,NK]
__global__ void softmax_rows(float* __restrict__ S, const unsigned char* __restrict__ mask)
{
    size_t row = blockIdx.x;
    int n = (int)(row % NQ);
    float* Sr = S + row * NK;
    const unsigned char* mr = mask ? (mask + (size_t)n * NK) : nullptr;
    int t = threadIdx.x;
    float vals[4];
    float mx = -3.4e38f;
    #pragma unroll
    for (int j = 0; j < 4; j++) {
        int i = t + j * 256;
        float v = Sr[i];
        if (mr && !mr[i]) v = -3.4e38f;
        vals[j] = v;
        mx = fmaxf(mx, v);
    }
    #pragma unroll
    for (int off = 16; off; off >>= 1) mx = fmaxf(mx, __shfl_xor_sync(0xffffffffu, mx, off));
    __shared__ float sh[8];
    int w = t >> 5, l = t & 31;
    if (l == 0) sh[w] = mx;
    __syncthreads();
    if (w == 0) {
        mx = (l < 8) ? sh[l] : -3.4e38f;
        #pragma unroll
        for (int off = 4; off; off >>= 1) mx = fmaxf(mx, __shfl_xor_sync(0xffffffffu, mx, off));
        if (l == 0) sh[0] = mx;
    }
    __syncthreads();
    mx = sh[0];
    float sum = 0.f;
    #pragma unroll
    for (int j = 0; j < 4; j++) {
        float e = __expf(vals[j] - mx);
        vals[j] = e;
        sum += e;
    }
    #pragma unroll
    for (int off = 16; off; off >>= 1) sum += __shfl_xor_sync(0xffffffffu, sum, off);
    __shared__ float sh2[8];
    if (l == 0) sh2[w] = sum;
    __syncthreads();
    if (w == 0) {
        sum = (l < 8) ? sh2[l] : 0.f;
        #pragma unroll
        for (int off = 4; off; off >>= 1) sum += __shfl_xor_sync(0xffffffffu, sum, off);
        if (l == 0) sh2[0] = sum;
    }
    __syncthreads();
    float inv = 1.0f / sh2[0];
    #pragma unroll
    for (int j = 0; j < 4; j++) Sr[t + j * 256] = vals[j] * inv;
}

// ------------------------------- A @ V -------------------------------------
__global__ void attn_av(const float* __restrict__ S, const float* __restrict__ V,
                        float* __restrict__ O, size_t vBatch, int vRow)
{
    int bh = blockIdx.z;
    int b = bh / Hh, h = bh % Hh;
    const float* Sb = S + (size_t)bh * NQ * NK;
    const float* Vb = V + (size_t)b * vBatch + h * HD;
    float* Ob = O + (size_t)b * NQ * Cc + h * HD;
    int n0 = blockIdx.y * 64;
    __shared__ float As[64][17];   // [n][m]
    __shared__ float Bs[16][68];   // [m][d]
    int t = threadIdx.x;
    int tx = t & 15, ty = t >> 4;
    float acc[4][4] = {};
    int lrow = t >> 2, lcol = (t & 3) * 4;   // S tile loader
    int vr = t >> 4, vc = (t & 15) * 4;       // V tile loader
    for (int k0 = 0; k0 < NK; k0 += 16) {
        float4 s4 = *(const float4*)(Sb + (size_t)(n0 + lrow) * NK + k0 + lcol);
        As[lrow][lcol] = s4.x; As[lrow][lcol+1] = s4.y; As[lrow][lcol+2] = s4.z; As[lrow][lcol+3] = s4.w;
        float4 v4 = *(const float4*)(Vb + (size_t)(k0 + vr) * vRow + vc);
        Bs[vr][vc] = v4.x; Bs[vr][vc+1] = v4.y; Bs[vr][vc+2] = v4.z; Bs[vr][vc+3] = v4.w;
        __syncthreads();
        #pragma unroll
        for (int kk = 0; kk < 16; kk++) {
            float ra[4], rb[4];
            #pragma unroll
            for (int i = 0; i < 4; i++) ra[i] = As[ty * 4 + i][kk];
            #pragma unroll
            for (int j = 0; j < 4; j++) rb[j] = Bs[kk][tx * 4 + j];
            #pragma unroll
            for (int i = 0; i < 4; i++)
                #pragma unroll
                for (int j = 0; j < 4; j++)
                    acc[i][j] += ra[i] * rb[j];
        }
        __syncthreads();
    }
    #pragma unroll
    for (int i = 0; i < 4; i++)
        #pragma unroll
        for (int j = 0; j < 4; j++)
            Ob[(size_t)(n0 + ty * 4 + i) * Cc + tx * 4 + j] = acc[i][j];
}

// ------------------------------ copy (y) -----------------------------------
__global__ void copy4_kernel(const float4* __restrict__ src, float4* __restrict__ dst, int n4)
{
    int i = blockIdx.x * blockDim.x + threadIdx.x;
    if (i < n4) dst[i] = src[i];
}

// ----------------------------- launch --------------------------------------
extern "C" void kernel_launch(void* const* d_in, const int* in_sizes, int n_in,
                              void* d_out, int out_size)
{
    const float* x        = (const float*)d_in[0];
    const float* y        = (const float*)d_in[1];
    const void*  mask_raw = d_in[4];
    const float* qkv_w    = (const float*)d_in[5];
    const float* aproj_w  = (const float*)d_in[6];
    const float* aproj_b  = (const float*)d_in[7];
    const float* q_w      = (const float*)d_in[8];
    const float* k_w      = (const float*)d_in[9];
    const float* v_w      = (const float*)d_in[10];
    const float* cproj_w  = (const float*)d_in[11];
    const float* cproj_b  = (const float*)d_in[12];
    const float* fc1_w    = (const float*)d_in[13];
    const float* fc1_b    = (const float*)d_in[14];
    const float* fc2_w    = (const float*)d_in[15];
    const float* fc2_b    = (const float*)d_in[16];
    const float* ln1_g    = (const float*)d_in[17];
    const float* ln1_b    = (const float*)d_in[18];
    const float* ln2_g    = (const float*)d_in[19];
    const float* ln2_b    = (const float*)d_in[20];
    const float* ln3_g    = (const float*)d_in[21];
    const float* ln3_b    = (const float*)d_in[22];
    const float* lny_g    = (const float*)d_in[23];
    const float* lny_b    = (const float*)d_in[24];
    float* out = (float*)d_out;

    float *p_ln, *p_qkv, *p_s, *p_ao, *p_x1, *p_x2, *p_yln, *p_q, *p_k, *p_v, *p_h1;
    unsigned char* p_mask;
    cudaGetSymbolAddress((void**)&p_ln,  g_ln);
    cudaGetSymbolAddress((void**)&p_qkv, g_qkv);
    cudaGetSymbolAddress((void**)&p_s,   g_scores);
    cudaGetSymbolAddress((void**)&p_ao,  g_attno);
    cudaGetSymbolAddress((void**)&p_x1,  g_x1);
    cudaGetSymbolAddress((void**)&p_x2,  g_x2);
    cudaGetSymbolAddress((void**)&p_yln, g_yln);
    cudaGetSymbolAddress((void**)&p_q,   g_q);
    cudaGetSymbolAddress((void**)&p_k,   g_k);
    cudaGetSymbolAddress((void**)&p_v,   g_v);
    cudaGetSymbolAddress((void**)&p_h1,  g_h1);
    cudaGetSymbolAddress((void**)&p_mask, g_mask);

    dim3 t256(256);
    dim3 gScore(NK / 64, NQ / 64, Bb * Hh);
    dim3 gAV(1, NQ / 64, Bb * Hh);

    // ---- mask decode (int32 vs u8 auto-detect) ----
    mask_detect<<<1, 256>>>((const unsigned int*)mask_raw);
    mask_decode<<<(NQ * NK + 255) / 256, t256>>>(mask_raw);

    // ---- self attention ----
    ln_kernel<<<MROWS, t256>>>(x, ln1_g, ln1_b, p_ln);
    gemm_nt<<<dim3(3 * Cc / 64, MROWS / 64), t256>>>(p_ln, qkv_w, p_qkv,
        MROWS, 3 * Cc, Cc, nullptr, nullptr, 0);
    attn_scores<<<gScore, t256>>>(p_qkv, p_qkv + Cc, p_s,
        (size_t)NQ * 3 * Cc, (size_t)NQ * 3 * Cc, 3 * Cc, 3 * Cc);
    softmax_rows<<<Bb * Hh * NQ, t256>>>(p_s, nullptr);
    attn_av<<<gAV, t256>>>(p_s, p_qkv + 2 * Cc, p_ao, (size_t)NQ * 3 * Cc, 3 * Cc);
    gemm_nt<<<dim3(Cc / 64, MROWS / 64), t256>>>(p_ao, aproj_w, p_x1,
        MROWS, Cc, Cc, aproj_b, x, 0);

    // ---- cross attention ----
    ln_kernel<<<MROWS, t256>>>(p_x1, ln2_g, ln2_b, p_ln);
    ln_kernel<<<MROWS, t256>>>(y, lny_g, lny_b, p_yln);
    gemm_nt<<<dim3(Cc / 64, MROWS / 64), t256>>>(p_ln,  q_w, p_q, MROWS, Cc, Cc, nullptr, nullptr, 0);
    gemm_nt<<<dim3(Cc / 64, MROWS / 64), t256>>>(p_yln, k_w, p_k, MROWS, Cc, Cc, nullptr, nullptr, 0);
    gemm_nt<<<dim3(Cc / 64, MROWS / 64), t256>>>(p_yln, v_w, p_v, MROWS, Cc, Cc, nullptr, nullptr, 0);
    attn_scores<<<gScore, t256>>>(p_q, p_k, p_s,
        (size_t)NQ * Cc, (size_t)NK * Cc, Cc, Cc);
    softmax_rows<<<Bb * Hh * NQ, t256>>>(p_s, p_mask);
    attn_av<<<gAV, t256>>>(p_s, p_v, p_ao, (size_t)NK * Cc, Cc);
    gemm_nt<<<dim3(Cc / 64, MROWS / 64), t256>>>(p_ao, cproj_w, p_x2,
        MROWS, Cc, Cc, cproj_b, p_x1, 0);

    // ---- MLP ----
    ln_kernel<<<MROWS, t256>>>(p_x2, ln3_g, ln3_b, p_ln);
    gemm_nt<<<dim3(HID / 64, MROWS / 64), t256>>>(p_ln, fc1_w, p_h1,
        MROWS, HID, Cc, fc1_b, nullptr, 1);
    gemm_nt<<<dim3(Cc / 64, MROWS / 64), t256>>>(p_h1, fc2_w, out,
        MROWS, Cc, HID, fc2_b, p_x2, 0);

    // ---- y passthrough ----
    int n4 = (MROWS * Cc) / 4;
    copy4_kernel<<<(n4 + 255) / 256, t256>>>((const float4*)y,
        (float4*)(out + (size_t)MROWS * Cc), n4);
}

// round 4
// speedup vs baseline: 1.6820x; 1.6820x over previous
#include <cuda_runtime.h>
#include <cuda_bf16.h>
#include <math.h>
#include <stdint.h>

// ---------------------------------------------------------------------------
// DinoDecoderBlock: B=8, NQ=NK=1024, C=768, H=12, HD=64, HID=3072
// Round 4: projection/MLP GEMMs on legacy HMMA (mma.sync bf16, bf16x3 split,
// cp.async 2-stage pipeline). tcgen05 is unavailable (harness targets sm_103
// without the 'a' suffix). Attention stays fp32 SIMT this round.
// ---------------------------------------------------------------------------

#define Bb   8
#define NQ   1024
#define NK   1024
#define Cc   768
#define Hh   12
#define HD   64
#define HID  3072
#define MROWS (Bb*NQ)          // 8192
#define SCALE 0.125f

// ------------------------- scratch (no allocs allowed) ---------------------
__device__ float g_qkv  [(size_t)MROWS*3*Cc];
__device__ float g_scores[(size_t)Bb*Hh*NQ*NK];       // 402 MB
__device__ float g_x1   [(size_t)MROWS*Cc];
__device__ float g_x2   [(size_t)MROWS*Cc];
__device__ float g_q    [(size_t)MROWS*Cc];
__device__ float g_k    [(size_t)MROWS*Cc];
__device__ float g_v    [(size_t)MROWS*Cc];

__device__ __nv_bfloat16 g_ln_hi [(size_t)MROWS*Cc];
__device__ __nv_bfloat16 g_ln_lo [(size_t)MROWS*Cc];
__device__ __nv_bfloat16 g_yln_hi[(size_t)MROWS*Cc];
__device__ __nv_bfloat16 g_yln_lo[(size_t)MROWS*Cc];
__device__ __nv_bfloat16 g_ao_hi [(size_t)MROWS*Cc];
__device__ __nv_bfloat16 g_ao_lo [(size_t)MROWS*Cc];
__device__ __nv_bfloat16 g_h1_hi [(size_t)MROWS*HID];
__device__ __nv_bfloat16 g_h1_lo [(size_t)MROWS*HID];

// all weights concatenated (hi/lo bf16)
#define W_QKV   0u
#define W_APROJ 1769472u
#define W_Q     2359296u
#define W_K     2949120u
#define W_V     3538944u
#define W_CPROJ 4128768u
#define W_FC1   4718592u
#define W_FC2   7077888u
#define W_TOT   9437184u
__device__ __nv_bfloat16 g_w_hi[W_TOT];
__device__ __nv_bfloat16 g_w_lo[W_TOT];

__device__ unsigned char g_mask[(size_t)NQ*NK];
__device__ int g_mask_is_u8;

// --------------------------- PTX helpers -----------------------------------
__device__ __forceinline__ uint32_t smem_u32(const void* p) {
    uint32_t a;
    asm("{ .reg .u64 t; cvta.to.shared.u64 t, %1; cvt.u32.u64 %0, t; }"
        : "=r"(a) : "l"(p));
    return a;
}
__device__ __forceinline__ void cp16(uint32_t dst, const void* src) {
    asm volatile("cp.async.cg.shared.global [%0], [%1], 16;" :: "r"(dst), "l"(src));
}
#define CP_COMMIT() asm volatile("cp.async.commit_group;" ::: "memory")
#define CP_WAIT(n)  asm volatile("cp.async.wait_group %0;" :: "n"(n) : "memory")

__device__ __forceinline__ void ldm_x4(uint32_t* r, uint32_t addr) {
    asm volatile("ldmatrix.sync.aligned.m8n8.x4.shared.b16 {%0,%1,%2,%3}, [%4];"
                 : "=r"(r[0]), "=r"(r[1]), "=r"(r[2]), "=r"(r[3]) : "r"(addr));
}
__device__ __forceinline__ void ldm_x2(uint32_t* r, uint32_t addr) {
    asm volatile("ldmatrix.sync.aligned.m8n8.x2.shared.b16 {%0,%1}, [%2];"
                 : "=r"(r[0]), "=r"(r[1]) : "r"(addr));
}
__device__ __forceinline__ void mma_bf16(float* d, const uint32_t* a, const uint32_t* b) {
    asm volatile(
        "mma.sync.aligned.m16n8k16.row.col.f32.bf16.bf16.f32 "
        "{%0,%1,%2,%3}, {%4,%5,%6,%7}, {%8,%9}, {%0,%1,%2,%3};"
        : "+f"(d[0]), "+f"(d[1]), "+f"(d[2]), "+f"(d[3])
        : "r"(a[0]), "r"(a[1]), "r"(a[2]), "r"(a[3]), "r"(b[0]), "r"(b[1]));
}

__device__ __forceinline__ void split_bf16(float x, __nv_bfloat16& h, __nv_bfloat16& l) {
    h = __float2bfloat16_rn(x);
    l = __float2bfloat16_rn(x - __bfloat162float(h));
}

// --------------------------- mask detect/decode ----------------------------
__global__ void mask_detect(const unsigned int* __restrict__ m)
{
    __shared__ int flag;
    if (threadIdx.x == 0) flag = 0;
    __syncthreads();
    for (int i = threadIdx.x; i < 65536; i += blockDim.x)
        if (m[i] > 1u) flag = 1;
    __syncthreads();
    if (threadIdx.x == 0) g_mask_is_u8 = flag;
}
__global__ void mask_decode(const void* __restrict__ msrc)
{
    size_t i = (size_t)blockIdx.x * blockDim.x + threadIdx.x;
    if (i >= (size_t)NQ * NK) return;
    unsigned char v;
    if (g_mask_is_u8) v = ((const unsigned char*)msrc)[i] ? 1 : 0;
    else              v = ((const int*)msrc)[i] ? 1 : 0;
    g_mask[i] = v;
}

// --------------------------- weight convert --------------------------------
__global__ void wconvert(const float* __restrict__ src, unsigned int off, int n)
{
    int i = blockIdx.x * blockDim.x + threadIdx.x;
    if (i >= n) return;
    __nv_bfloat16 h, l;
    split_bf16(src[i], h, l);
    g_w_hi[off + i] = h;
    g_w_lo[off + i] = l;
}

// ------------------------------ LayerNorm ----------------------------------
__global__ void ln_kernel(const float* __restrict__ X, const float* __restrict__ g,
                          const float* __restrict__ b,
                          __nv_bfloat16* __restrict__ Oh, __nv_bfloat16* __restrict__ Ol)
{
    int row = blockIdx.x;
    const float* x = X + (size_t)row * Cc;
    int t = threadIdx.x;
    float v0 = x[t], v1 = x[t + 256], v2 = x[t + 512];
    float s  = v0 + v1 + v2;
    float s2 = v0*v0 + v1*v1 + v2*v2;
    #pragma unroll
    for (int off = 16; off; off >>= 1) {
        s  += __shfl_xor_sync(0xffffffffu, s,  off);
        s2 += __shfl_xor_sync(0xffffffffu, s2, off);
    }
    __shared__ float shs[8], shs2[8];
    int w = t >> 5, l = t & 31;
    if (l == 0) { shs[w] = s; shs2[w] = s2; }
    __syncthreads();
    if (w == 0) {
        s  = (l < 8) ? shs[l]  : 0.f;
        s2 = (l < 8) ? shs2[l] : 0.f;
        #pragma unroll
        for (int off = 4; off; off >>= 1) {
            s  += __shfl_xor_sync(0xffffffffu, s,  off);
            s2 += __shfl_xor_sync(0xffffffffu, s2, off);
        }
        if (l == 0) { shs[0] = s; shs2[0] = s2; }
    }
    __syncthreads();
    float mean = shs[0] * (1.f / Cc);
    float var  = shs2[0] * (1.f / Cc) - mean * mean;
    float inv  = rsqrtf(var + 1e-5f);
    size_t base = (size_t)row * Cc;
    #pragma unroll
    for (int j = 0; j < 3; j++) {
        int c = t + j * 256;
        float v = (j == 0 ? v0 : (j == 1 ? v1 : v2));
        float o = (v - mean) * inv * g[c] + b[c];
        __nv_bfloat16 h, lo;
        split_bf16(o, h, lo);
        Oh[base + c] = h;
        Ol[base + c] = lo;
    }
}

// --------------------------- HMMA GEMM -------------------------------------
// C[M,N] = A[M,K] @ W[N,K]^T (bf16x3 split) + epilogue.
// 256 threads, tile 128x128, BK=32, 2-stage cp.async pipeline.
// SMEM per stage: 4 tiles of [128][40] bf16 (rows padded 32->40 for ldmatrix
// bank-conflict freedom). grid(N/128, M/128).
#define PADR 40
#define TILE_B (128 * PADR * 2)       // 10240 bytes
#define STAGE_B (4 * TILE_B)          // 40960 bytes
#define GSM_TOTAL (2 * STAGE_B)       // 81920 bytes

__global__ void __launch_bounds__(256, 1) gemm_tc(
    const __nv_bfloat16* __restrict__ Ah, const __nv_bfloat16* __restrict__ Al,
    const __nv_bfloat16* __restrict__ Bh, const __nv_bfloat16* __restrict__ Bl,
    int K, int N,
    const float* __restrict__ bias, const float* __restrict__ res, int gelu,
    float* __restrict__ outF,
    __nv_bfloat16* __restrict__ outH, __nv_bfloat16* __restrict__ outL)
{
    extern __shared__ char smem[];
    uint32_t smb = smem_u32(smem);
    int tid = threadIdx.x;
    int wid = tid >> 5, lane = tid & 31;
    int wm = wid >> 2, wn = wid & 3;            // warp tile: 64x32
    int m0 = blockIdx.y * 128;
    int n0 = blockIdx.x * 128;

    // loader mapping: per tile 512 chunks of 16B; 2 per thread
    int lr0 = tid >> 2;             // rows 0..63
    int lc  = (tid & 3) << 3;       // elem offsets 0,8,16,24

    float acc[4][4][4];
    #pragma unroll
    for (int i = 0; i < 4; i++)
        #pragma unroll
        for (int j = 0; j < 4; j++)
            #pragma unroll
            for (int r = 0; r < 4; r++) acc[i][j][r] = 0.f;

    int NIT = K >> 5;

    // ---- stage loader ----
    auto load_stage = [&](int it, int s) {
        int k0 = it << 5;
        uint32_t sb = smb + s * STAGE_B;
        const __nv_bfloat16* srcs[4] = { Ah, Al, Bh, Bl };
        #pragma unroll
        for (int tgt = 0; tgt < 4; tgt++) {
            const __nv_bfloat16* base = srcs[tgt] +
                (size_t)((tgt < 2 ? m0 : n0)) * K + k0;
            uint32_t tb = sb + tgt * TILE_B;
            #pragma unroll
            for (int q = 0; q < 2; q++) {
                int row = lr0 + q * 64;
                cp16(tb + (uint32_t)(row * PADR + lc) * 2,
                     base + (size_t)row * K + lc);
            }
        }
    };

    load_stage(0, 0);
    CP_COMMIT();

    for (int it = 0; it < NIT; it++) {
        int s = it & 1;
        if (it + 1 < NIT) {
            load_stage(it + 1, s ^ 1);
            CP_COMMIT();
            CP_WAIT(1);
        } else {
            CP_WAIT(0);
        }
        __syncthreads();

        uint32_t sAh = smb + s * STAGE_B;
        uint32_t sAl = sAh + TILE_B;
        uint32_t sBh = sAh + 2 * TILE_B;
        uint32_t sBl = sAh + 3 * TILE_B;

        #pragma unroll
        for (int kk = 0; kk < 32; kk += 16) {
            uint32_t ah[4][4], al[4][4], bh[4][2], bl[4][2];
            int arow = lane & 15;
            int acol = kk + ((lane >> 4) << 3);
            #pragma unroll
            for (int i = 0; i < 4; i++) {
                uint32_t off = (uint32_t)((wm * 64 + i * 16 + arow) * PADR + acol) * 2;
                ldm_x4(ah[i], sAh + off);
                ldm_x4(al[i], sAl + off);
            }
            int brow = lane & 7;
            int bcol = kk + ((lane >> 3) & 1) * 8;
            #pragma unroll
            for (int j = 0; j < 4; j++) {
                uint32_t off = (uint32_t)((wn * 32 + j * 8 + brow) * PADR + bcol) * 2;
                ldm_x2(bh[j], sBh + off);
                ldm_x2(bl[j], sBl + off);
            }
            #pragma unroll
            for (int i = 0; i < 4; i++)
                #pragma unroll
                for (int j = 0; j < 4; j++) {
                    mma_bf16(acc[i][j], ah[i], bh[j]);
                    mma_bf16(acc[i][j], ah[i], bl[j]);
                    mma_bf16(acc[i][j], al[i], bh[j]);
                }
        }
        __syncthreads();
    }

    // ---- epilogue: direct register writes ----
    #pragma unroll
    for (int i = 0; i < 4; i++) {
        #pragma unroll
        for (int j = 0; j < 4; j++) {
            int mb = m0 + wm * 64 + i * 16 + (lane >> 2);
            int nb = n0 + wn * 32 + j * 8 + (lane & 3) * 2;
            #pragma unroll
            for (int half = 0; half < 2; half++) {
                int m = mb + half * 8;
                float v0 = acc[i][j][half * 2 + 0];
                float v1 = acc[i][j][half * 2 + 1];
                if (bias) { v0 += bias[nb]; v1 += bias[nb + 1]; }
                if (gelu) {
                    v0 = 0.5f * v0 * (1.0f + erff(v0 * 0.70710678118654752f));
                    v1 = 0.5f * v1 * (1.0f + erff(v1 * 0.70710678118654752f));
                }
                size_t gi = (size_t)m * N + nb;
                if (res) {
                    float2 r2 = *(const float2*)(res + gi);
                    v0 += r2.x; v1 += r2.y;
                }
                if (outF) {
                    float2 o2 = make_float2(v0, v1);
                    *(float2*)(outF + gi) = o2;
                }
                if (outH) {
                    __nv_bfloat16 h0, l0, h1, l1;
                    split_bf16(v0, h0, l0);
                    split_bf16(v1, h1, l1);
                    __nv_bfloat162 hh; hh.x = h0; hh.y = h1;
                    __nv_bfloat162 ll; ll.x = l0; ll.y = l1;
                    *(__nv_bfloat162*)(outH + gi) = hh;
                    *(__nv_bfloat162*)(outL + gi) = ll;
                }
            }
        }
    }
}

// --------------------------- attention scores ------------------------------
__global__ void attn_scores(const float* __restrict__ Q, const float* __restrict__ Kp,
                            float* __restrict__ S, size_t qBatch, size_t kBatch,
                            int qRow, int kRow)
{
    int bh = blockIdx.z;
    int b = bh / Hh, h = bh % Hh;
    const float* Qb = Q + (size_t)b * qBatch + h * HD;
    const float* Kb = Kp + (size_t)b * kBatch + h * HD;
    float* Sb = S + (size_t)bh * NQ * NK;
    __shared__ float Qs[64][65];
    __shared__ float Ks[64][65];
    int n0 = blockIdx.y * 64, m0 = blockIdx.x * 64;
    int t = threadIdx.x;
    #pragma unroll
    for (int i = 0; i < 4; i++) {
        int idx = t + i * 256;
        int r = idx >> 4;
        int c = (idx & 15) * 4;
        float4 q4 = *(const float4*)(Qb + (size_t)(n0 + r) * qRow + c);
        Qs[r][c] = q4.x; Qs[r][c+1] = q4.y; Qs[r][c+2] = q4.z; Qs[r][c+3] = q4.w;
        float4 k4 = *(const float4*)(Kb + (size_t)(m0 + r) * kRow + c);
        Ks[r][c] = k4.x; Ks[r][c+1] = k4.y; Ks[r][c+2] = k4.z; Ks[r][c+3] = k4.w;
    }
    __syncthreads();
    int tx = t & 15, ty = t >> 4;
    float acc[4][4] = {};
    #pragma unroll 8
    for (int kk = 0; kk < 64; kk++) {
        float ra[4], rb[4];
        #pragma unroll
        for (int i = 0; i < 4; i++) ra[i] = Qs[ty * 4 + i][kk];
        #pragma unroll
        for (int j = 0; j < 4; j++) rb[j] = Ks[tx * 4 + j][kk];
        #pragma unroll
        for (int i = 0; i < 4; i++)
            #pragma unroll
            for (int j = 0; j < 4; j++)
                acc[i][j] += ra[i] * rb[j];
    }
    #pragma unroll
    for (int i = 0; i < 4; i++)
        #pragma unroll
        for (int j = 0; j < 4; j++)
            Sb[(size_t)(n0 + ty * 4 + i) * NK + m0 + tx * 4 + j] = acc[i][j] * SCALE;
}

// ------------------------------- softmax -----------------------------------
__global__ void softmax_rows(float* __restrict__ S, const unsigned char* __restrict__ mask)
{
    size_t row = blockIdx.x;
    int n = (int)(row % NQ);
    float* Sr = S + row * NK;
    const unsigned char* mr = mask ? (mask + (size_t)n * NK) : nullptr;
    int t = threadIdx.x;
    float vals[4];
    float mx = -3.4e38f;
    #pragma unroll
    for (int j = 0; j < 4; j++) {
        int i = t + j * 256;
        float v = Sr[i];
        if (mr && !mr[i]) v = -3.4e38f;
        vals[j] = v;
        mx = fmaxf(mx, v);
    }
    #pragma unroll
    for (int off = 16; off; off >>= 1) mx = fmaxf(mx, __shfl_xor_sync(0xffffffffu, mx, off));
    __shared__ float sh[8];
    int w = t >> 5, l = t & 31;
    if (l == 0) sh[w] = mx;
    __syncthreads();
    if (w == 0) {
        mx = (l < 8) ? sh[l] : -3.4e38f;
        #pragma unroll
        for (int off = 4; off; off >>= 1) mx = fmaxf(mx, __shfl_xor_sync(0xffffffffu, mx, off));
        if (l == 0) sh[0] = mx;
    }
    __syncthreads();
    mx = sh[0];
    float sum = 0.f;
    #pragma unroll
    for (int j = 0; j < 4; j++) {
        float e = __expf(vals[j] - mx);
        vals[j] = e;
        sum += e;
    }
    #pragma unroll
    for (int off = 16; off; off >>= 1) sum += __shfl_xor_sync(0xffffffffu, sum, off);
    __shared__ float sh2[8];
    if (l == 0) sh2[w] = sum;
    __syncthreads();
    if (w == 0) {
        sum = (l < 8) ? sh2[l] : 0.f;
        #pragma unroll
        for (int off = 4; off; off >>= 1) sum += __shfl_xor_sync(0xffffffffu, sum, off);
        if (l == 0) sh2[0] = sum;
    }
    __syncthreads();
    float inv = 1.0f / sh2[0];
    #pragma unroll
    for (int j = 0; j < 4; j++) Sr[t + j * 256] = vals[j] * inv;
}

// ------------------------------- A @ V -------------------------------------
__global__ void attn_av(const float* __restrict__ S, const float* __restrict__ V,
                        __nv_bfloat16* __restrict__ Oh, __nv_bfloat16* __restrict__ Ol,
                        size_t vBatch, int vRow)
{
    int bh = blockIdx.z;
    int b = bh / Hh, h = bh % Hh;
    const float* Sb = S + (size_t)bh * NQ * NK;
    const float* Vb = V + (size_t)b * vBatch + h * HD;
    size_t obase = (size_t)b * NQ * Cc + h * HD;
    int n0 = blockIdx.y * 64;
    __shared__ float As[64][17];
    __shared__ float Bs[16][68];
    int t = threadIdx.x;
    int tx = t & 15, ty = t >> 4;
    float acc[4][4] = {};
    int lrow = t >> 2, lcol = (t & 3) * 4;
    int vr = t >> 4, vc = (t & 15) * 4;
    for (int k0 = 0; k0 < NK; k0 += 16) {
        float4 s4 = *(const float4*)(Sb + (size_t)(n0 + lrow) * NK + k0 + lcol);
        As[lrow][lcol] = s4.x; As[lrow][lcol+1] = s4.y; As[lrow][lcol+2] = s4.z; As[lrow][lcol+3] = s4.w;
        float4 v4 = *(const float4*)(Vb + (size_t)(k0 + vr) * vRow + vc);
        Bs[vr][vc] = v4.x; Bs[vr][vc+1] = v4.y; Bs[vr][vc+2] = v4.z; Bs[vr][vc+3] = v4.w;
        __syncthreads();
        #pragma unroll
        for (int kk = 0; kk < 16; kk++) {
            float ra[4], rb[4];
            #pragma unroll
            for (int i = 0; i < 4; i++) ra[i] = As[ty * 4 + i][kk];
            #pragma unroll
            for (int j = 0; j < 4; j++) rb[j] = Bs[kk][tx * 4 + j];
            #pragma unroll
            for (int i = 0; i < 4; i++)
                #pragma unroll
                for (int j = 0; j < 4; j++)
                    acc[i][j] += ra[i] * rb[j];
        }
        __syncthreads();
    }
    #pragma unroll
    for (int i = 0; i < 4; i++)
        #pragma unroll
        for (int j = 0; j < 4; j++) {
            size_t gi = obase + (size_t)(n0 + ty * 4 + i) * Cc + tx * 4 + j;
            __nv_bfloat16 hh, ll;
            split_bf16(acc[i][j], hh, ll);
            Oh[gi] = hh;
            Ol[gi] = ll;
        }
}

// ------------------------------ copy (y) -----------------------------------
__global__ void copy4_kernel(const float4* __restrict__ src, float4* __restrict__ dst, int n4)
{
    int i = blockIdx.x * blockDim.x + threadIdx.x;
    if (i < n4) dst[i] = src[i];
}

// ----------------------------- launch --------------------------------------
extern "C" void kernel_launch(void* const* d_in, const int* in_sizes, int n_in,
                              void* d_out, int out_size)
{
    const float* x        = (const float*)d_in[0];
    const float* y        = (const float*)d_in[1];
    const void*  mask_raw = d_in[4];
    const float* qkv_w    = (const float*)d_in[5];
    const float* aproj_w  = (const float*)d_in[6];
    const float* aproj_b  = (const float*)d_in[7];
    const float* q_w      = (const float*)d_in[8];
    const float* k_w      = (const float*)d_in[9];
    const float* v_w      = (const float*)d_in[10];
    const float* cproj_w  = (const float*)d_in[11];
    const float* cproj_b  = (const float*)d_in[12];
    const float* fc1_w    = (const float*)d_in[13];
    const float* fc1_b    = (const float*)d_in[14];
    const float* fc2_w    = (const float*)d_in[15];
    const float* fc2_b    = (const float*)d_in[16];
    const float* ln1_g    = (const float*)d_in[17];
    const float* ln1_b    = (const float*)d_in[18];
    const float* ln2_g    = (const float*)d_in[19];
    const float* ln2_b    = (const float*)d_in[20];
    const float* ln3_g    = (const float*)d_in[21];
    const float* ln3_b    = (const float*)d_in[22];
    const float* lny_g    = (const float*)d_in[23];
    const float* lny_b    = (const float*)d_in[24];
    float* out = (float*)d_out;

    float *p_qkv, *p_s, *p_x1, *p_x2, *p_q, *p_k, *p_v;
    __nv_bfloat16 *p_lnh, *p_lnl, *p_ylnh, *p_ylnl, *p_aoh, *p_aol, *p_h1h, *p_h1l, *p_wh, *p_wl;
    unsigned char* p_mask;
    cudaGetSymbolAddress((void**)&p_qkv, g_qkv);
    cudaGetSymbolAddress((void**)&p_s,   g_scores);
    cudaGetSymbolAddress((void**)&p_x1,  g_x1);
    cudaGetSymbolAddress((void**)&p_x2,  g_x2);
    cudaGetSymbolAddress((void**)&p_q,   g_q);
    cudaGetSymbolAddress((void**)&p_k,   g_k);
    cudaGetSymbolAddress((void**)&p_v,   g_v);
    cudaGetSymbolAddress((void**)&p_lnh, g_ln_hi);
    cudaGetSymbolAddress((void**)&p_lnl, g_ln_lo);
    cudaGetSymbolAddress((void**)&p_ylnh, g_yln_hi);
    cudaGetSymbolAddress((void**)&p_ylnl, g_yln_lo);
    cudaGetSymbolAddress((void**)&p_aoh, g_ao_hi);
    cudaGetSymbolAddress((void**)&p_aol, g_ao_lo);
    cudaGetSymbolAddress((void**)&p_h1h, g_h1_hi);
    cudaGetSymbolAddress((void**)&p_h1l, g_h1_lo);
    cudaGetSymbolAddress((void**)&p_wh,  g_w_hi);
    cudaGetSymbolAddress((void**)&p_wl,  g_w_lo);
    cudaGetSymbolAddress((void**)&p_mask, g_mask);

    cudaFuncSetAttribute(gemm_tc, cudaFuncAttributeMaxDynamicSharedMemorySize, GSM_TOTAL);

    dim3 t256(256);
    dim3 gScore(NK / 64, NQ / 64, Bb * Hh);
    dim3 gAV(1, NQ / 64, Bb * Hh);

    // ---- weight conversion ----
    {
        const int tb = 256;
        wconvert<<<(1769472 + tb - 1) / tb, tb>>>(qkv_w,   W_QKV,   1769472);
        wconvert<<<(589824  + tb - 1) / tb, tb>>>(aproj_w, W_APROJ, 589824);
        wconvert<<<(589824  + tb - 1) / tb, tb>>>(q_w,     W_Q,     589824);
        wconvert<<<(589824  + tb - 1) / tb, tb>>>(k_w,     W_K,     589824);
        wconvert<<<(589824  + tb - 1) / tb, tb>>>(v_w,     W_V,     589824);
        wconvert<<<(589824  + tb - 1) / tb, tb>>>(cproj_w, W_CPROJ, 589824);
        wconvert<<<(2359296 + tb - 1) / tb, tb>>>(fc1_w,   W_FC1,   2359296);
        wconvert<<<(2359296 + tb - 1) / tb, tb>>>(fc2_w,   W_FC2,   2359296);
    }

    // ---- mask decode ----
    mask_detect<<<1, 256>>>((const unsigned int*)mask_raw);
    mask_decode<<<(NQ * NK + 255) / 256, t256>>>(mask_raw);

    // ---- self attention ----
    ln_kernel<<<MROWS, t256>>>(x, ln1_g, ln1_b, p_lnh, p_lnl);
    gemm_tc<<<dim3(3 * Cc / 128, MROWS / 128), t256, GSM_TOTAL>>>(
        p_lnh, p_lnl, p_wh + W_QKV, p_wl + W_QKV, Cc, 3 * Cc,
        nullptr, nullptr, 0, p_qkv, nullptr, nullptr);
    attn_scores<<<gScore, t256>>>(p_qkv, p_qkv + Cc, p_s,
        (size_t)NQ * 3 * Cc, (size_t)NQ * 3 * Cc, 3 * Cc, 3 * Cc);
    softmax_rows<<<Bb * Hh * NQ, t256>>>(p_s, nullptr);
    attn_av<<<gAV, t256>>>(p_s, p_qkv + 2 * Cc, p_aoh, p_aol, (size_t)NQ * 3 * Cc, 3 * Cc);
    gemm_tc<<<dim3(Cc / 128, MROWS / 128), t256, GSM_TOTAL>>>(
        p_aoh, p_aol, p_wh + W_APROJ, p_wl + W_APROJ, Cc, Cc,
        aproj_b, x, 0, p_x1, nullptr, nullptr);

    // ---- cross attention ----
    ln_kernel<<<MROWS, t256>>>(p_x1, ln2_g, ln2_b, p_lnh, p_lnl);
    ln_kernel<<<MROWS, t256>>>(y, lny_g, lny_b, p_ylnh, p_ylnl);
    gemm_tc<<<dim3(Cc / 128, MROWS / 128), t256, GSM_TOTAL>>>(
        p_lnh, p_lnl, p_wh + W_Q, p_wl + W_Q, Cc, Cc,
        nullptr, nullptr, 0, p_q, nullptr, nullptr);
    gemm_tc<<<dim3(Cc / 128, MROWS / 128), t256, GSM_TOTAL>>>(
        p_ylnh, p_ylnl, p_wh + W_K, p_wl + W_K, Cc, Cc,
        nullptr, nullptr, 0, p_k, nullptr, nullptr);
    gemm_tc<<<dim3(Cc / 128, MROWS / 128), t256, GSM_TOTAL>>>(
        p_ylnh, p_ylnl, p_wh + W_V, p_wl + W_V, Cc, Cc,
        nullptr, nullptr, 0, p_v, nullptr, nullptr);
    attn_scores<<<gScore, t256>>>(p_q, p_k, p_s,
        (size_t)NQ * Cc, (size_t)NK * Cc, Cc, Cc);
    softmax_rows<<<Bb * Hh * NQ, t256>>>(p_s, p_mask);
    attn_av<<<gAV, t256>>>(p_s, p_v, p_aoh, p_aol, (size_t)NK * Cc, Cc);
    gemm_tc<<<dim3(Cc / 128, MROWS / 128), t256, GSM_TOTAL>>>(
        p_aoh, p_aol, p_wh + W_CPROJ, p_wl + W_CPROJ, Cc, Cc,
        cproj_b, p_x1, 0, p_x2, nullptr, nullptr);

    // ---- MLP ----
    ln_kernel<<<MROWS, t256>>>(p_x2, ln3_g, ln3_b, p_lnh, p_lnl);
    gemm_tc<<<dim3(HID / 128, MROWS / 128), t256, GSM_TOTAL>>>(
        p_lnh, p_lnl, p_wh + W_FC1, p_wl + W_FC1, Cc, HID,
        fc1_b, nullptr, 1, nullptr, p_h1h, p_h1l);
    gemm_tc<<<dim3(Cc / 128, MROWS / 128), t256, GSM_TOTAL>>>(
        p_h1h, p_h1l, p_wh + W_FC2, p_wl + W_FC2, HID, Cc,
        fc2_b, p_x2, 0, out, nullptr, nullptr);

    // ---- y passthrough ----
    int n4 = (MROWS * Cc) / 4;
    copy4_kernel<<<(n4 + 255) / 256, t256>>>((const float4*)y,
        (float4*)(out + (size_t)MROWS * Cc), n4);
}

// round 5
// speedup vs baseline: 3.1641x; 1.8811x over previous
#include <cuda_runtime.h>
#include <cuda_bf16.h>
#include <math.h>
#include <stdint.h>

// ---------------------------------------------------------------------------
// DinoDecoderBlock: B=8, NQ=NK=1024, C=768, H=12, HD=64, HID=3072
// Round 5: fused flash-attention on HMMA (bf16 QK^T + online softmax + PV),
// no materialized scores. Projection/MLP GEMMs stay HMMA bf16x3.
// ---------------------------------------------------------------------------

#define Bb   8
#define NQ   1024
#define NKk  1024
#define Cc   768
#define Hh   12
#define HD   64
#define HID  3072
#define MROWS (Bb*NQ)          // 8192
#define SCALE 0.125f

// ------------------------- scratch (no allocs allowed) ---------------------
__device__ float g_x1   [(size_t)MROWS*Cc];
__device__ float g_x2   [(size_t)MROWS*Cc];

__device__ __nv_bfloat16 g_qkvb [(size_t)MROWS*3*Cc];   // self-attn QKV bf16
__device__ __nv_bfloat16 g_qb   [(size_t)MROWS*Cc];
__device__ __nv_bfloat16 g_kb   [(size_t)MROWS*Cc];
__device__ __nv_bfloat16 g_vb   [(size_t)MROWS*Cc];

__device__ __nv_bfloat16 g_ln_hi [(size_t)MROWS*Cc];
__device__ __nv_bfloat16 g_ln_lo [(size_t)MROWS*Cc];
__device__ __nv_bfloat16 g_yln_hi[(size_t)MROWS*Cc];
__device__ __nv_bfloat16 g_yln_lo[(size_t)MROWS*Cc];
__device__ __nv_bfloat16 g_ao_hi [(size_t)MROWS*Cc];
__device__ __nv_bfloat16 g_ao_lo [(size_t)MROWS*Cc];
__device__ __nv_bfloat16 g_h1_hi [(size_t)MROWS*HID];
__device__ __nv_bfloat16 g_h1_lo [(size_t)MROWS*HID];

// all weights concatenated (hi/lo bf16)
#define W_QKV   0u
#define W_APROJ 1769472u
#define W_Q     2359296u
#define W_K     2949120u
#define W_V     3538944u
#define W_CPROJ 4128768u
#define W_FC1   4718592u
#define W_FC2   7077888u
#define W_TOT   9437184u
__device__ __nv_bfloat16 g_w_hi[W_TOT];
__device__ __nv_bfloat16 g_w_lo[W_TOT];

__device__ unsigned char g_mask[(size_t)NQ*NKk];
__device__ int g_mask_is_u8;

// --------------------------- PTX helpers -----------------------------------
__device__ __forceinline__ uint32_t smem_u32(const void* p) {
    uint32_t a;
    asm("{ .reg .u64 t; cvta.to.shared.u64 t, %1; cvt.u32.u64 %0, t; }"
        : "=r"(a) : "l"(p));
    return a;
}
__device__ __forceinline__ void cp16(uint32_t dst, const void* src) {
    asm volatile("cp.async.cg.shared.global [%0], [%1], 16;" :: "r"(dst), "l"(src));
}
#define CP_COMMIT() asm volatile("cp.async.commit_group;" ::: "memory")
#define CP_WAIT(n)  asm volatile("cp.async.wait_group %0;" :: "n"(n) : "memory")

__device__ __forceinline__ void ldm_x4(uint32_t* r, uint32_t addr) {
    asm volatile("ldmatrix.sync.aligned.m8n8.x4.shared.b16 {%0,%1,%2,%3}, [%4];"
                 : "=r"(r[0]), "=r"(r[1]), "=r"(r[2]), "=r"(r[3]) : "r"(addr));
}
__device__ __forceinline__ void ldm_x2(uint32_t* r, uint32_t addr) {
    asm volatile("ldmatrix.sync.aligned.m8n8.x2.shared.b16 {%0,%1}, [%2];"
                 : "=r"(r[0]), "=r"(r[1]) : "r"(addr));
}
__device__ __forceinline__ void ldm_x2t(uint32_t* r, uint32_t addr) {
    asm volatile("ldmatrix.sync.aligned.m8n8.x2.trans.shared.b16 {%0,%1}, [%2];"
                 : "=r"(r[0]), "=r"(r[1]) : "r"(addr));
}
__device__ __forceinline__ void mma_bf16(float* d, const uint32_t* a, const uint32_t* b) {
    asm volatile(
        "mma.sync.aligned.m16n8k16.row.col.f32.bf16.bf16.f32 "
        "{%0,%1,%2,%3}, {%4,%5,%6,%7}, {%8,%9}, {%0,%1,%2,%3};"
        : "+f"(d[0]), "+f"(d[1]), "+f"(d[2]), "+f"(d[3])
        : "r"(a[0]), "r"(a[1]), "r"(a[2]), "r"(a[3]), "r"(b[0]), "r"(b[1]));
}

__device__ __forceinline__ void split_bf16(float x, __nv_bfloat16& h, __nv_bfloat16& l) {
    h = __float2bfloat16_rn(x);
    l = __float2bfloat16_rn(x - __bfloat162float(h));
}
__device__ __forceinline__ uint32_t packbf(float a, float b) {
    __nv_bfloat162 t = __floats2bfloat162_rn(a, b);
    return *(uint32_t*)&t;
}

// --------------------------- mask detect/decode ----------------------------
__global__ void mask_detect(const unsigned int* __restrict__ m)
{
    __shared__ int flag;
    if (threadIdx.x == 0) flag = 0;
    __syncthreads();
    for (int i = threadIdx.x; i < 65536; i += blockDim.x)
        if (m[i] > 1u) flag = 1;
    __syncthreads();
    if (threadIdx.x == 0) g_mask_is_u8 = flag;
}
__global__ void mask_decode(const void* __restrict__ msrc)
{
    size_t i = (size_t)blockIdx.x * blockDim.x + threadIdx.x;
    if (i >= (size_t)NQ * NKk) return;
    unsigned char v;
    if (g_mask_is_u8) v = ((const unsigned char*)msrc)[i] ? 1 : 0;
    else              v = ((const int*)msrc)[i] ? 1 : 0;
    g_mask[i] = v;
}

// --------------------------- weight convert --------------------------------
__global__ void wconvert(const float* __restrict__ src, unsigned int off, int n)
{
    int i = blockIdx.x * blockDim.x + threadIdx.x;
    if (i >= n) return;
    __nv_bfloat16 h, l;
    split_bf16(src[i], h, l);
    g_w_hi[off + i] = h;
    g_w_lo[off + i] = l;
}

// ------------------------------ LayerNorm ----------------------------------
__global__ void ln_kernel(const float* __restrict__ X, const float* __restrict__ g,
                          const float* __restrict__ b,
                          __nv_bfloat16* __restrict__ Oh, __nv_bfloat16* __restrict__ Ol)
{
    int row = blockIdx.x;
    const float* x = X + (size_t)row * Cc;
    int t = threadIdx.x;
    float v0 = x[t], v1 = x[t + 256], v2 = x[t + 512];
    float s  = v0 + v1 + v2;
    float s2 = v0*v0 + v1*v1 + v2*v2;
    #pragma unroll
    for (int off = 16; off; off >>= 1) {
        s  += __shfl_xor_sync(0xffffffffu, s,  off);
        s2 += __shfl_xor_sync(0xffffffffu, s2, off);
    }
    __shared__ float shs[8], shs2[8];
    int w = t >> 5, l = t & 31;
    if (l == 0) { shs[w] = s; shs2[w] = s2; }
    __syncthreads();
    if (w == 0) {
        s  = (l < 8) ? shs[l]  : 0.f;
        s2 = (l < 8) ? shs2[l] : 0.f;
        #pragma unroll
        for (int off = 4; off; off >>= 1) {
            s  += __shfl_xor_sync(0xffffffffu, s,  off);
            s2 += __shfl_xor_sync(0xffffffffu, s2, off);
        }
        if (l == 0) { shs[0] = s; shs2[0] = s2; }
    }
    __syncthreads();
    float mean = shs[0] * (1.f / Cc);
    float var  = shs2[0] * (1.f / Cc) - mean * mean;
    float inv  = rsqrtf(var + 1e-5f);
    size_t base = (size_t)row * Cc;
    #pragma unroll
    for (int j = 0; j < 3; j++) {
        int c = t + j * 256;
        float v = (j == 0 ? v0 : (j == 1 ? v1 : v2));
        float o = (v - mean) * inv * g[c] + b[c];
        __nv_bfloat16 h, lo;
        split_bf16(o, h, lo);
        Oh[base + c] = h;
        Ol[base + c] = lo;
    }
}

// --------------------------- HMMA GEMM -------------------------------------
// C[M,N] = A[M,K] @ W[N,K]^T (bf16x3 split) + epilogue.
#define PADR 40
#define TILE_B (128 * PADR * 2)       // 10240 bytes
#define STAGE_B (4 * TILE_B)          // 40960 bytes
#define GSM_TOTAL (2 * STAGE_B)       // 81920 bytes

__global__ void __launch_bounds__(256, 1) gemm_tc(
    const __nv_bfloat16* __restrict__ Ah, const __nv_bfloat16* __restrict__ Al,
    const __nv_bfloat16* __restrict__ Bh, const __nv_bfloat16* __restrict__ Bl,
    int K, int N,
    const float* __restrict__ bias, const float* __restrict__ res, int gelu,
    float* __restrict__ outF,
    __nv_bfloat16* __restrict__ outH, __nv_bfloat16* __restrict__ outL)
{
    extern __shared__ char smem[];
    uint32_t smb = smem_u32(smem);
    int tid = threadIdx.x;
    int wid = tid >> 5, lane = tid & 31;
    int wm = wid >> 2, wn = wid & 3;            // warp tile: 64x32
    int m0 = blockIdx.y * 128;
    int n0 = blockIdx.x * 128;

    int lr0 = tid >> 2;
    int lc  = (tid & 3) << 3;

    float acc[4][4][4];
    #pragma unroll
    for (int i = 0; i < 4; i++)
        #pragma unroll
        for (int j = 0; j < 4; j++)
            #pragma unroll
            for (int r = 0; r < 4; r++) acc[i][j][r] = 0.f;

    int NIT = K >> 5;

    auto load_stage = [&](int it, int s) {
        int k0 = it << 5;
        uint32_t sb = smb + s * STAGE_B;
        const __nv_bfloat16* srcs[4] = { Ah, Al, Bh, Bl };
        #pragma unroll
        for (int tgt = 0; tgt < 4; tgt++) {
            const __nv_bfloat16* base = srcs[tgt] +
                (size_t)((tgt < 2 ? m0 : n0)) * K + k0;
            uint32_t tb = sb + tgt * TILE_B;
            #pragma unroll
            for (int q = 0; q < 2; q++) {
                int row = lr0 + q * 64;
                cp16(tb + (uint32_t)(row * PADR + lc) * 2,
                     base + (size_t)row * K + lc);
            }
        }
    };

    load_stage(0, 0);
    CP_COMMIT();

    for (int it = 0; it < NIT; it++) {
        int s = it & 1;
        if (it + 1 < NIT) {
            load_stage(it + 1, s ^ 1);
            CP_COMMIT();
            CP_WAIT(1);
        } else {
            CP_WAIT(0);
        }
        __syncthreads();

        uint32_t sAh = smb + s * STAGE_B;
        uint32_t sAl = sAh + TILE_B;
        uint32_t sBh = sAh + 2 * TILE_B;
        uint32_t sBl = sAh + 3 * TILE_B;

        #pragma unroll
        for (int kk = 0; kk < 32; kk += 16) {
            uint32_t ah[4][4], al[4][4], bh[4][2], bl[4][2];
            int arow = lane & 15;
            int acol = kk + ((lane >> 4) << 3);
            #pragma unroll
            for (int i = 0; i < 4; i++) {
                uint32_t off = (uint32_t)((wm * 64 + i * 16 + arow) * PADR + acol) * 2;
                ldm_x4(ah[i], sAh + off);
                ldm_x4(al[i], sAl + off);
            }
            int brow = lane & 7;
            int bcol = kk + ((lane >> 3) & 1) * 8;
            #pragma unroll
            for (int j = 0; j < 4; j++) {
                uint32_t off = (uint32_t)((wn * 32 + j * 8 + brow) * PADR + bcol) * 2;
                ldm_x2(bh[j], sBh + off);
                ldm_x2(bl[j], sBl + off);
            }
            #pragma unroll
            for (int i = 0; i < 4; i++)
                #pragma unroll
                for (int j = 0; j < 4; j++) {
                    mma_bf16(acc[i][j], ah[i], bh[j]);
                    mma_bf16(acc[i][j], ah[i], bl[j]);
                    mma_bf16(acc[i][j], al[i], bh[j]);
                }
        }
        __syncthreads();
    }

    #pragma unroll
    for (int i = 0; i < 4; i++) {
        #pragma unroll
        for (int j = 0; j < 4; j++) {
            int mb = m0 + wm * 64 + i * 16 + (lane >> 2);
            int nb = n0 + wn * 32 + j * 8 + (lane & 3) * 2;
            #pragma unroll
            for (int half = 0; half < 2; half++) {
                int m = mb + half * 8;
                float v0 = acc[i][j][half * 2 + 0];
                float v1 = acc[i][j][half * 2 + 1];
                if (bias) { v0 += bias[nb]; v1 += bias[nb + 1]; }
                if (gelu) {
                    v0 = 0.5f * v0 * (1.0f + erff(v0 * 0.70710678118654752f));
                    v1 = 0.5f * v1 * (1.0f + erff(v1 * 0.70710678118654752f));
                }
                size_t gi = (size_t)m * N + nb;
                if (res) {
                    float2 r2 = *(const float2*)(res + gi);
                    v0 += r2.x; v1 += r2.y;
                }
                if (outF) {
                    float2 o2 = make_float2(v0, v1);
                    *(float2*)(outF + gi) = o2;
                }
                if (outH) {
                    __nv_bfloat16 h0, l0, h1, l1;
                    split_bf16(v0, h0, l0);
                    split_bf16(v1, h1, l1);
                    __nv_bfloat162 hh; hh.x = h0; hh.y = h1;
                    *(__nv_bfloat162*)(outH + gi) = hh;
                    if (outL) {
                        __nv_bfloat162 ll; ll.x = l0; ll.y = l1;
                        *(__nv_bfloat162*)(outL + gi) = ll;
                    }
                }
            }
        }
    }
}

// --------------------------- flash attention --------------------------------
// One CTA: 128 Q rows x full KV (1024). 8 warps, 16 Q rows/warp.
// Q/K/V bf16; S=QK^T via HMMA, online softmax, P@V via HMMA (V trans-ldmatrix).
// Output: hi/lo bf16 split [B,NQ,C].
#define FA_PAD 72
#define FS_Q  0u
#define FS_K  18432u            // 2 stages x 9216
#define FS_V  36864u            // 2 stages x 9216
#define FS_M  55296u            // 2 stages x 8192
#define FA_SMEM 71680u

__global__ void __launch_bounds__(256, 1) flash_attn(
    const __nv_bfloat16* __restrict__ Qsrc, const __nv_bfloat16* __restrict__ Ksrc,
    const __nv_bfloat16* __restrict__ Vsrc,
    size_t qBatch, size_t kvBatch, int qStride, int kvStride,
    const unsigned char* __restrict__ maskp,
    __nv_bfloat16* __restrict__ Oh, __nv_bfloat16* __restrict__ Ol)
{
    extern __shared__ char smem[];
    uint32_t smb = smem_u32(smem);
    int tid = threadIdx.x;
    int wid = tid >> 5, lane = tid & 31;
    int wq = wid << 4;                    // warp's Q row base (0..112)
    int bh = blockIdx.y;
    int b = bh / Hh, h = bh % Hh;
    int qrow0 = blockIdx.x * 128;

    const __nv_bfloat16* Qb = Qsrc + (size_t)b * qBatch + h * HD;
    const __nv_bfloat16* Kb = Ksrc + (size_t)b * kvBatch + h * HD;
    const __nv_bfloat16* Vb = Vsrc + (size_t)b * kvBatch + h * HD;

    auto load_kv = [&](int t, int s) {
        #pragma unroll
        for (int j2 = 0; j2 < 2; j2++) {
            int idx = tid + j2 * 256;
            int r = idx >> 3, c = (idx & 7) << 3;
            cp16(smb + FS_K + s * 9216u + (uint32_t)(r * FA_PAD + c) * 2,
                 Kb + (size_t)(t * 64 + r) * kvStride + c);
            cp16(smb + FS_V + s * 9216u + (uint32_t)(r * FA_PAD + c) * 2,
                 Vb + (size_t)(t * 64 + r) * kvStride + c);
        }
        if (maskp) {
            #pragma unroll
            for (int j2 = 0; j2 < 2; j2++) {
                int idx = tid + j2 * 256;
                int r = idx >> 2, c = (idx & 3) << 4;
                cp16(smb + FS_M + s * 8192u + (uint32_t)(r * 64 + c),
                     maskp + (size_t)(qrow0 + r) * NKk + t * 64 + c);
            }
        }
    };

    // Q tile load (group 0 with KV stage 0)
    #pragma unroll
    for (int j4 = 0; j4 < 4; j4++) {
        int idx = tid + j4 * 256;
        int r = idx >> 3, c = (idx & 7) << 3;
        cp16(smb + FS_Q + (uint32_t)(r * FA_PAD + c) * 2,
             Qb + (size_t)(qrow0 + r) * qStride + c);
    }
    load_kv(0, 0);
    CP_COMMIT();

    uint32_t Aq[4][4];
    float O[8][4];
    #pragma unroll
    for (int j = 0; j < 8; j++)
        #pragma unroll
        for (int e = 0; e < 4; e++) O[j][e] = 0.f;
    float m0 = -1e30f, m1 = -1e30f, l0 = 0.f, l1 = 0.f;

    int r0l = wq + (lane >> 2);          // local q row, d0/d1
    int cb2 = (lane & 3) * 2;

    for (int t = 0; t < 16; t++) {
        int s = t & 1;
        if (t + 1 < 16) {
            load_kv(t + 1, s ^ 1);
            CP_COMMIT();
            CP_WAIT(1);
        } else {
            CP_WAIT(0);
        }
        __syncthreads();

        if (t == 0) {
            #pragma unroll
            for (int kc = 0; kc < 4; kc++) {
                uint32_t off = (uint32_t)((wq + (lane & 15)) * FA_PAD
                               + kc * 16 + ((lane >> 4) << 3)) * 2;
                ldm_x4(Aq[kc], smb + FS_Q + off);
            }
        }

        // ---- S = Q @ K^T ----
        float S[8][4];
        #pragma unroll
        for (int j = 0; j < 8; j++)
            #pragma unroll
            for (int e = 0; e < 4; e++) S[j][e] = 0.f;
        uint32_t sK = smb + FS_K + s * 9216u;
        #pragma unroll
        for (int kc = 0; kc < 4; kc++) {
            #pragma unroll
            for (int j = 0; j < 8; j++) {
                uint32_t bk[2];
                uint32_t off = (uint32_t)((8 * j + (lane & 7)) * FA_PAD
                               + 16 * kc + ((lane >> 3) & 1) * 8) * 2;
                ldm_x2(bk, sK + off);
                mma_bf16(S[j], Aq[kc], bk);
            }
        }

        // ---- scale + mask ----
        const unsigned char* sM = (const unsigned char*)(smem + FS_M + s * 8192u);
        #pragma unroll
        for (int j = 0; j < 8; j++) {
            S[j][0] *= SCALE; S[j][1] *= SCALE;
            S[j][2] *= SCALE; S[j][3] *= SCALE;
            if (maskp) {
                int col = 8 * j + cb2;
                unsigned short mw0 = *(const unsigned short*)(sM + r0l * 64 + col);
                unsigned short mw1 = *(const unsigned short*)(sM + (r0l + 8) * 64 + col);
                if (!(mw0 & 0xFF))   S[j][0] = -1e9f;
                if (!(mw0 >> 8))     S[j][1] = -1e9f;
                if (!(mw1 & 0xFF))   S[j][2] = -1e9f;
                if (!(mw1 >> 8))     S[j][3] = -1e9f;
            }
        }

        // ---- online softmax ----
        float mx0 = -1e30f, mx1 = -1e30f;
        #pragma unroll
        for (int j = 0; j < 8; j++) {
            mx0 = fmaxf(mx0, fmaxf(S[j][0], S[j][1]));
            mx1 = fmaxf(mx1, fmaxf(S[j][2], S[j][3]));
        }
        mx0 = fmaxf(mx0, __shfl_xor_sync(0xffffffffu, mx0, 1));
        mx0 = fmaxf(mx0, __shfl_xor_sync(0xffffffffu, mx0, 2));
        mx1 = fmaxf(mx1, __shfl_xor_sync(0xffffffffu, mx1, 1));
        mx1 = fmaxf(mx1, __shfl_xor_sync(0xffffffffu, mx1, 2));
        float mn0 = fmaxf(m0, mx0), mn1 = fmaxf(m1, mx1);
        float a0 = __expf(m0 - mn0), a1 = __expf(m1 - mn1);
        float sum0 = 0.f, sum1 = 0.f;
        #pragma unroll
        for (int j = 0; j < 8; j++) {
            S[j][0] = __expf(S[j][0] - mn0); sum0 += S[j][0];
            S[j][1] = __expf(S[j][1] - mn0); sum0 += S[j][1];
            S[j][2] = __expf(S[j][2] - mn1); sum1 += S[j][2];
            S[j][3] = __expf(S[j][3] - mn1); sum1 += S[j][3];
        }
        l0 = l0 * a0 + sum0;
        l1 = l1 * a1 + sum1;
        m0 = mn0; m1 = mn1;
        #pragma unroll
        for (int j = 0; j < 8; j++) {
            O[j][0] *= a0; O[j][1] *= a0;
            O[j][2] *= a1; O[j][3] *= a1;
        }

        // ---- O += P @ V ----
        uint32_t sV = smb + FS_V + s * 9216u;
        #pragma unroll
        for (int kc = 0; kc < 4; kc++) {
            uint32_t Ap[4];
            Ap[0] = packbf(S[2 * kc][0],     S[2 * kc][1]);
            Ap[1] = packbf(S[2 * kc][2],     S[2 * kc][3]);
            Ap[2] = packbf(S[2 * kc + 1][0], S[2 * kc + 1][1]);
            Ap[3] = packbf(S[2 * kc + 1][2], S[2 * kc + 1][3]);
            #pragma unroll
            for (int j = 0; j < 8; j++) {
                uint32_t bv[2];
                uint32_t off = (uint32_t)((16 * kc + (lane & 15)) * FA_PAD + 8 * j) * 2;
                ldm_x2t(bv, sV + off);
                mma_bf16(O[j], Ap, bv);
            }
        }
        __syncthreads();
    }

    // ---- epilogue ----
    l0 += __shfl_xor_sync(0xffffffffu, l0, 1);
    l0 += __shfl_xor_sync(0xffffffffu, l0, 2);
    l1 += __shfl_xor_sync(0xffffffffu, l1, 1);
    l1 += __shfl_xor_sync(0xffffffffu, l1, 2);
    float inv0 = 1.f / l0, inv1 = 1.f / l1;
    int grow0 = qrow0 + r0l;
    size_t obase = (size_t)b * NQ * Cc + (size_t)h * HD;
    #pragma unroll
    for (int j = 0; j < 8; j++) {
        int col = 8 * j + cb2;
        float v0 = O[j][0] * inv0, v1 = O[j][1] * inv0;
        float v2 = O[j][2] * inv1, v3 = O[j][3] * inv1;
        __nv_bfloat16 h0, l0b, h1, l1b;
        size_t gi0 = obase + (size_t)grow0 * Cc + col;
        split_bf16(v0, h0, l0b); split_bf16(v1, h1, l1b);
        { __nv_bfloat162 hh; hh.x = h0; hh.y = h1; *(__nv_bfloat162*)(Oh + gi0) = hh; }
        { __nv_bfloat162 ll; ll.x = l0b; ll.y = l1b; *(__nv_bfloat162*)(Ol + gi0) = ll; }
        size_t gi1 = obase + (size_t)(grow0 + 8) * Cc + col;
        split_bf16(v2, h0, l0b); split_bf16(v3, h1, l1b);
        { __nv_bfloat162 hh; hh.x = h0; hh.y = h1; *(__nv_bfloat162*)(Oh + gi1) = hh; }
        { __nv_bfloat162 ll; ll.x = l0b; ll.y = l1b; *(__nv_bfloat162*)(Ol + gi1) = ll; }
    }
}

// ------------------------------ copy (y) -----------------------------------
__global__ void copy4_kernel(const float4* __restrict__ src, float4* __restrict__ dst, int n4)
{
    int i = blockIdx.x * blockDim.x + threadIdx.x;
    if (i < n4) dst[i] = src[i];
}

// ----------------------------- launch --------------------------------------
extern "C" void kernel_launch(void* const* d_in, const int* in_sizes, int n_in,
                              void* d_out, int out_size)
{
    const float* x        = (const float*)d_in[0];
    const float* y        = (const float*)d_in[1];
    const void*  mask_raw = d_in[4];
    const float* qkv_w    = (const float*)d_in[5];
    const float* aproj_w  = (const float*)d_in[6];
    const float* aproj_b  = (const float*)d_in[7];
    const float* q_w      = (const float*)d_in[8];
    const float* k_w      = (const float*)d_in[9];
    const float* v_w      = (const float*)d_in[10];
    const float* cproj_w  = (const float*)d_in[11];
    const float* cproj_b  = (const float*)d_in[12];
    const float* fc1_w    = (const float*)d_in[13];
    const float* fc1_b    = (const float*)d_in[14];
    const float* fc2_w    = (const float*)d_in[15];
    const float* fc2_b    = (const float*)d_in[16];
    const float* ln1_g    = (const float*)d_in[17];
    const float* ln1_b    = (const float*)d_in[18];
    const float* ln2_g    = (const float*)d_in[19];
    const float* ln2_b    = (const float*)d_in[20];
    const float* ln3_g    = (const float*)d_in[21];
    const float* ln3_b    = (const float*)d_in[22];
    const float* lny_g    = (const float*)d_in[23];
    const float* lny_b    = (const float*)d_in[24];
    float* out = (float*)d_out;

    float *p_x1, *p_x2;
    __nv_bfloat16 *p_qkvb, *p_qb, *p_kb, *p_vb;
    __nv_bfloat16 *p_lnh, *p_lnl, *p_ylnh, *p_ylnl, *p_aoh, *p_aol, *p_h1h, *p_h1l, *p_wh, *p_wl;
    unsigned char* p_mask;
    cudaGetSymbolAddress((void**)&p_x1,  g_x1);
    cudaGetSymbolAddress((void**)&p_x2,  g_x2);
    cudaGetSymbolAddress((void**)&p_qkvb, g_qkvb);
    cudaGetSymbolAddress((void**)&p_qb,  g_qb);
    cudaGetSymbolAddress((void**)&p_kb,  g_kb);
    cudaGetSymbolAddress((void**)&p_vb,  g_vb);
    cudaGetSymbolAddress((void**)&p_lnh, g_ln_hi);
    cudaGetSymbolAddress((void**)&p_lnl, g_ln_lo);
    cudaGetSymbolAddress((void**)&p_ylnh, g_yln_hi);
    cudaGetSymbolAddress((void**)&p_ylnl, g_yln_lo);
    cudaGetSymbolAddress((void**)&p_aoh, g_ao_hi);
    cudaGetSymbolAddress((void**)&p_aol, g_ao_lo);
    cudaGetSymbolAddress((void**)&p_h1h, g_h1_hi);
    cudaGetSymbolAddress((void**)&p_h1l, g_h1_lo);
    cudaGetSymbolAddress((void**)&p_wh,  g_w_hi);
    cudaGetSymbolAddress((void**)&p_wl,  g_w_lo);
    cudaGetSymbolAddress((void**)&p_mask, g_mask);

    cudaFuncSetAttribute(gemm_tc, cudaFuncAttributeMaxDynamicSharedMemorySize, GSM_TOTAL);
    cudaFuncSetAttribute(flash_attn, cudaFuncAttributeMaxDynamicSharedMemorySize, FA_SMEM);

    dim3 t256(256);
    dim3 gFlash(NQ / 128, Bb * Hh);

    // ---- weight conversion ----
    {
        const int tb = 256;
        wconvert<<<(1769472 + tb - 1) / tb, tb>>>(qkv_w,   W_QKV,   1769472);
        wconvert<<<(589824  + tb - 1) / tb, tb>>>(aproj_w, W_APROJ, 589824);
        wconvert<<<(589824  + tb - 1) / tb, tb>>>(q_w,     W_Q,     589824);
        wconvert<<<(589824  + tb - 1) / tb, tb>>>(k_w,     W_K,     589824);
        wconvert<<<(589824  + tb - 1) / tb, tb>>>(v_w,     W_V,     589824);
        wconvert<<<(589824  + tb - 1) / tb, tb>>>(cproj_w, W_CPROJ, 589824);
        wconvert<<<(2359296 + tb - 1) / tb, tb>>>(fc1_w,   W_FC1,   2359296);
        wconvert<<<(2359296 + tb - 1) / tb, tb>>>(fc2_w,   W_FC2,   2359296);
    }

    // ---- mask decode ----
    mask_detect<<<1, 256>>>((const unsigned int*)mask_raw);
    mask_decode<<<(NQ * NKk + 255) / 256, t256>>>(mask_raw);

    // ---- self attention ----
    ln_kernel<<<MROWS, t256>>>(x, ln1_g, ln1_b, p_lnh, p_lnl);
    gemm_tc<<<dim3(3 * Cc / 128, MROWS / 128), t256, GSM_TOTAL>>>(
        p_lnh, p_lnl, p_wh + W_QKV, p_wl + W_QKV, Cc, 3 * Cc,
        nullptr, nullptr, 0, nullptr, p_qkvb, nullptr);
    flash_attn<<<gFlash, t256, FA_SMEM>>>(
        p_qkvb, p_qkvb + Cc, p_qkvb + 2 * Cc,
        (size_t)NQ * 3 * Cc, (size_t)NQ * 3 * Cc, 3 * Cc, 3 * Cc,
        nullptr, p_aoh, p_aol);
    gemm_tc<<<dim3(Cc / 128, MROWS / 128), t256, GSM_TOTAL>>>(
        p_aoh, p_aol, p_wh + W_APROJ, p_wl + W_APROJ, Cc, Cc,
        aproj_b, x, 0, p_x1, nullptr, nullptr);

    // ---- cross attention ----
    ln_kernel<<<MROWS, t256>>>(p_x1, ln2_g, ln2_b, p_lnh, p_lnl);
    ln_kernel<<<MROWS, t256>>>(y, lny_g, lny_b, p_ylnh, p_ylnl);
    gemm_tc<<<dim3(Cc / 128, MROWS / 128), t256, GSM_TOTAL>>>(
        p_lnh, p_lnl, p_wh + W_Q, p_wl + W_Q, Cc, Cc,
        nullptr, nullptr, 0, nullptr, p_qb, nullptr);
    gemm_tc<<<dim3(Cc / 128, MROWS / 128), t256, GSM_TOTAL>>>(
        p_ylnh, p_ylnl, p_wh + W_K, p_wl + W_K, Cc, Cc,
        nullptr, nullptr, 0, nullptr, p_kb, nullptr);
    gemm_tc<<<dim3(Cc / 128, MROWS / 128), t256, GSM_TOTAL>>>(
        p_ylnh, p_ylnl, p_wh + W_V, p_wl + W_V, Cc, Cc,
        nullptr, nullptr, 0, nullptr, p_vb, nullptr);
    flash_attn<<<gFlash, t256, FA_SMEM>>>(
        p_qb, p_kb, p_vb,
        (size_t)NQ * Cc, (size_t)NKk * Cc, Cc, Cc,
        p_mask, p_aoh, p_aol);
    gemm_tc<<<dim3(Cc / 128, MROWS / 128), t256, GSM_TOTAL>>>(
        p_aoh, p_aol, p_wh + W_CPROJ, p_wl + W_CPROJ, Cc, Cc,
        cproj_b, p_x1, 0, p_x2, nullptr, nullptr);

    // ---- MLP ----
    ln_kernel<<<MROWS, t256>>>(p_x2, ln3_g, ln3_b, p_lnh, p_lnl);
    gemm_tc<<<dim3(HID / 128, MROWS / 128), t256, GSM_TOTAL>>>(
        p_lnh, p_lnl, p_wh + W_FC1, p_wl + W_FC1, Cc, HID,
        fc1_b, nullptr, 1, nullptr, p_h1h, p_h1l);
    gemm_tc<<<dim3(Cc / 128, MROWS / 128), t256, GSM_TOTAL>>>(
        p_h1h, p_h1l, p_wh + W_FC2, p_wl + W_FC2, HID, Cc,
        fc2_b, p_x2, 0, out, nullptr, nullptr);

    // ---- y passthrough ----
    int n4 = (MROWS * Cc) / 4;
    copy4_kernel<<<(n4 + 255) / 256, t256>>>((const float4*)y,
        (float4*)(out + (size_t)MROWS * Cc), n4);
}

// round 6
// speedup vs baseline: 3.9702x; 1.2548x over previous
#include <cuda_runtime.h>
#include <cuda_fp16.h>
#include <math.h>
#include <stdint.h>

// ---------------------------------------------------------------------------
// DinoDecoderBlock: B=8, NQ=NK=1024, C=768, H=12, HD=64, HID=3072
// Round 6: fp16 2-term split GEMMs (A=hi+lo fp16, W single fp16; error is
// only weight rounding ~1.4e-4). Flash attention in fp16. K+V GEMM merged.
// Single wconvert kernel; launch order puts gemm_qkv at ncu sample index 5.
// ---------------------------------------------------------------------------

#define Bb   8
#define NQ   1024
#define NKk  1024
#define Cc   768
#define Hh   12
#define HD   64
#define HID  3072
#define MROWS (Bb*NQ)          // 8192
#define SCALE 0.125f

// ------------------------- scratch (no allocs allowed) ---------------------
__device__ float g_x1   [(size_t)MROWS*Cc];
__device__ float g_x2   [(size_t)MROWS*Cc];

__device__ __half g_qkvh [(size_t)MROWS*3*Cc];   // self-attn QKV fp16 (unsplit)
__device__ __half g_qh   [(size_t)MROWS*Cc];     // cross Q fp16
__device__ __half g_kvh  [(size_t)MROWS*2*Cc];   // cross K|V fp16 (merged)

__device__ __half g_ln_hi [(size_t)MROWS*Cc];
__device__ __half g_ln_lo [(size_t)MROWS*Cc];
__device__ __half g_yln_hi[(size_t)MROWS*Cc];
__device__ __half g_yln_lo[(size_t)MROWS*Cc];
__device__ __half g_ao_hi [(size_t)MROWS*Cc];
__device__ __half g_ao_lo [(size_t)MROWS*Cc];
__device__ __half g_h1_hi [(size_t)MROWS*HID];
__device__ __half g_h1_lo [(size_t)MROWS*HID];

// all weights concatenated (single fp16)
#define W_QKV   0u
#define W_APROJ 1769472u
#define W_Q     2359296u
#define W_K     2949120u
#define W_V     3538944u
#define W_CPROJ 4128768u
#define W_FC1   4718592u
#define W_FC2   7077888u
#define W_TOT   9437184u
__device__ __half g_w[W_TOT];

__device__ unsigned char g_mask[(size_t)NQ*NKk];
__device__ int g_mask_is_u8;

// --------------------------- PTX helpers -----------------------------------
__device__ __forceinline__ uint32_t smem_u32(const void* p) {
    uint32_t a;
    asm("{ .reg .u64 t; cvta.to.shared.u64 t, %1; cvt.u32.u64 %0, t; }"
        : "=r"(a) : "l"(p));
    return a;
}
__device__ __forceinline__ void cp16(uint32_t dst, const void* src) {
    asm volatile("cp.async.cg.shared.global [%0], [%1], 16;" :: "r"(dst), "l"(src));
}
#define CP_COMMIT() asm volatile("cp.async.commit_group;" ::: "memory")
#define CP_WAIT(n)  asm volatile("cp.async.wait_group %0;" :: "n"(n) : "memory")

__device__ __forceinline__ void ldm_x4(uint32_t* r, uint32_t addr) {
    asm volatile("ldmatrix.sync.aligned.m8n8.x4.shared.b16 {%0,%1,%2,%3}, [%4];"
                 : "=r"(r[0]), "=r"(r[1]), "=r"(r[2]), "=r"(r[3]) : "r"(addr));
}
__device__ __forceinline__ void ldm_x2(uint32_t* r, uint32_t addr) {
    asm volatile("ldmatrix.sync.aligned.m8n8.x2.shared.b16 {%0,%1}, [%2];"
                 : "=r"(r[0]), "=r"(r[1]) : "r"(addr));
}
__device__ __forceinline__ void ldm_x2t(uint32_t* r, uint32_t addr) {
    asm volatile("ldmatrix.sync.aligned.m8n8.x2.trans.shared.b16 {%0,%1}, [%2];"
                 : "=r"(r[0]), "=r"(r[1]) : "r"(addr));
}
__device__ __forceinline__ void mma_f16(float* d, const uint32_t* a, const uint32_t* b) {
    asm volatile(
        "mma.sync.aligned.m16n8k16.row.col.f32.f16.f16.f32 "
        "{%0,%1,%2,%3}, {%4,%5,%6,%7}, {%8,%9}, {%0,%1,%2,%3};"
        : "+f"(d[0]), "+f"(d[1]), "+f"(d[2]), "+f"(d[3])
        : "r"(a[0]), "r"(a[1]), "r"(a[2]), "r"(a[3]), "r"(b[0]), "r"(b[1]));
}

__device__ __forceinline__ void split_f16(float x, __half& h, __half& l) {
    h = __float2half_rn(x);
    l = __float2half_rn(x - __half2float(h));
}
__device__ __forceinline__ uint32_t packh(float a, float b) {
    __half2 t = __floats2half2_rn(a, b);
    return *(uint32_t*)&t;
}

// --------------------------- weight convert (one kernel) -------------------
__global__ void wconvert_all(
    const float* __restrict__ s0, const float* __restrict__ s1,
    const float* __restrict__ s2, const float* __restrict__ s3,
    const float* __restrict__ s4, const float* __restrict__ s5,
    const float* __restrict__ s6, const float* __restrict__ s7)
{
    unsigned int i = blockIdx.x * blockDim.x + threadIdx.x;
    if (i >= W_TOT) return;
    float v;
    if      (i < W_APROJ) v = s0[i - W_QKV];
    else if (i < W_Q)     v = s1[i - W_APROJ];
    else if (i < W_K)     v = s2[i - W_Q];
    else if (i < W_V)     v = s3[i - W_K];
    else if (i < W_CPROJ) v = s4[i - W_V];
    else if (i < W_FC1)   v = s5[i - W_CPROJ];
    else if (i < W_FC2)   v = s6[i - W_FC1];
    else                  v = s7[i - W_FC2];
    g_w[i] = __float2half_rn(v);
}

// --------------------------- mask detect/decode ----------------------------
__global__ void mask_detect(const unsigned int* __restrict__ m)
{
    __shared__ int flag;
    if (threadIdx.x == 0) flag = 0;
    __syncthreads();
    for (int i = threadIdx.x; i < 65536; i += blockDim.x)
        if (m[i] > 1u) flag = 1;
    __syncthreads();
    if (threadIdx.x == 0) g_mask_is_u8 = flag;
}
__global__ void mask_decode(const void* __restrict__ msrc)
{
    size_t i = (size_t)blockIdx.x * blockDim.x + threadIdx.x;
    if (i >= (size_t)NQ * NKk) return;
    unsigned char v;
    if (g_mask_is_u8) v = ((const unsigned char*)msrc)[i] ? 1 : 0;
    else              v = ((const int*)msrc)[i] ? 1 : 0;
    g_mask[i] = v;
}

// ------------------------------ LayerNorm ----------------------------------
__global__ void ln_kernel(const float* __restrict__ X, const float* __restrict__ g,
                          const float* __restrict__ b,
                          __half* __restrict__ Oh, __half* __restrict__ Ol)
{
    int row = blockIdx.x;
    const float* x = X + (size_t)row * Cc;
    int t = threadIdx.x;
    float v0 = x[t], v1 = x[t + 256], v2 = x[t + 512];
    float s  = v0 + v1 + v2;
    float s2 = v0*v0 + v1*v1 + v2*v2;
    #pragma unroll
    for (int off = 16; off; off >>= 1) {
        s  += __shfl_xor_sync(0xffffffffu, s,  off);
        s2 += __shfl_xor_sync(0xffffffffu, s2, off);
    }
    __shared__ float shs[8], shs2[8];
    int w = t >> 5, l = t & 31;
    if (l == 0) { shs[w] = s; shs2[w] = s2; }
    __syncthreads();
    if (w == 0) {
        s  = (l < 8) ? shs[l]  : 0.f;
        s2 = (l < 8) ? shs2[l] : 0.f;
        #pragma unroll
        for (int off = 4; off; off >>= 1) {
            s  += __shfl_xor_sync(0xffffffffu, s,  off);
            s2 += __shfl_xor_sync(0xffffffffu, s2, off);
        }
        if (l == 0) { shs[0] = s; shs2[0] = s2; }
    }
    __syncthreads();
    float mean = shs[0] * (1.f / Cc);
    float var  = shs2[0] * (1.f / Cc) - mean * mean;
    float inv  = rsqrtf(var + 1e-5f);
    size_t base = (size_t)row * Cc;
    #pragma unroll
    for (int j = 0; j < 3; j++) {
        int c = t + j * 256;
        float v = (j == 0 ? v0 : (j == 1 ? v1 : v2));
        float o = (v - mean) * inv * g[c] + b[c];
        __half h, lo;
        split_f16(o, h, lo);
        Oh[base + c] = h;
        Ol[base + c] = lo;
    }
}

// --------------------------- HMMA GEMM (fp16 2-term) -----------------------
// C[M,N] = (Ah+Al)[M,K] @ W[N,K]^T + epilogue. 256 threads, 128x128, BK=32.
#define PADR 40
#define TILE_B (128 * PADR * 2)       // 10240 bytes
#define STAGE_B (3 * TILE_B)          // 30720 bytes
#define GSM_TOTAL (2 * STAGE_B)       // 61440 bytes

__global__ void __launch_bounds__(256, 1) gemm_tc(
    const __half* __restrict__ Ah, const __half* __restrict__ Al,
    const __half* __restrict__ Bw,
    int K, int N,
    const float* __restrict__ bias, const float* __restrict__ res, int gelu,
    float* __restrict__ outF,
    __half* __restrict__ outH, __half* __restrict__ outL)
{
    extern __shared__ char smem[];
    uint32_t smb = smem_u32(smem);
    int tid = threadIdx.x;
    int wid = tid >> 5, lane = tid & 31;
    int wm = wid >> 2, wn = wid & 3;            // warp tile: 64x32
    int m0 = blockIdx.y * 128;
    int n0 = blockIdx.x * 128;

    int lr0 = tid >> 2;
    int lc  = (tid & 3) << 3;

    float acc[4][4][4];
    #pragma unroll
    for (int i = 0; i < 4; i++)
        #pragma unroll
        for (int j = 0; j < 4; j++)
            #pragma unroll
            for (int r = 0; r < 4; r++) acc[i][j][r] = 0.f;

    int NIT = K >> 5;

    auto load_stage = [&](int it, int s) {
        int k0 = it << 5;
        uint32_t sb = smb + s * STAGE_B;
        const __half* srcs[3] = { Ah, Al, Bw };
        #pragma unroll
        for (int tgt = 0; tgt < 3; tgt++) {
            const __half* base = srcs[tgt] +
                (size_t)((tgt < 2 ? m0 : n0)) * K + k0;
            uint32_t tb = sb + tgt * TILE_B;
            #pragma unroll
            for (int q = 0; q < 2; q++) {
                int row = lr0 + q * 64;
                cp16(tb + (uint32_t)(row * PADR + lc) * 2,
                     base + (size_t)row * K + lc);
            }
        }
    };

    load_stage(0, 0);
    CP_COMMIT();

    for (int it = 0; it < NIT; it++) {
        int s = it & 1;
        if (it + 1 < NIT) {
            load_stage(it + 1, s ^ 1);
            CP_COMMIT();
            CP_WAIT(1);
        } else {
            CP_WAIT(0);
        }
        __syncthreads();

        uint32_t sAh = smb + s * STAGE_B;
        uint32_t sAl = sAh + TILE_B;
        uint32_t sB  = sAh + 2 * TILE_B;

        #pragma unroll
        for (int kk = 0; kk < 32; kk += 16) {
            uint32_t ah[4][4], al[4][4], bw[4][2];
            int arow = lane & 15;
            int acol = kk + ((lane >> 4) << 3);
            #pragma unroll
            for (int i = 0; i < 4; i++) {
                uint32_t off = (uint32_t)((wm * 64 + i * 16 + arow) * PADR + acol) * 2;
                ldm_x4(ah[i], sAh + off);
                ldm_x4(al[i], sAl + off);
            }
            int brow = lane & 7;
            int bcol = kk + ((lane >> 3) & 1) * 8;
            #pragma unroll
            for (int j = 0; j < 4; j++) {
                uint32_t off = (uint32_t)((wn * 32 + j * 8 + brow) * PADR + bcol) * 2;
                ldm_x2(bw[j], sB + off);
            }
            #pragma unroll
            for (int i = 0; i < 4; i++)
                #pragma unroll
                for (int j = 0; j < 4; j++) {
                    mma_f16(acc[i][j], ah[i], bw[j]);
                    mma_f16(acc[i][j], al[i], bw[j]);
                }
        }
        __syncthreads();
    }

    #pragma unroll
    for (int i = 0; i < 4; i++) {
        #pragma unroll
        for (int j = 0; j < 4; j++) {
            int mb = m0 + wm * 64 + i * 16 + (lane >> 2);
            int nb = n0 + wn * 32 + j * 8 + (lane & 3) * 2;
            #pragma unroll
            for (int half = 0; half < 2; half++) {
                int m = mb + half * 8;
                float v0 = acc[i][j][half * 2 + 0];
                float v1 = acc[i][j][half * 2 + 1];
                if (bias) { v0 += bias[nb]; v1 += bias[nb + 1]; }
                if (gelu) {
                    v0 = 0.5f * v0 * (1.0f + erff(v0 * 0.70710678118654752f));
                    v1 = 0.5f * v1 * (1.0f + erff(v1 * 0.70710678118654752f));
                }
                size_t gi = (size_t)m * N + nb;
                if (res) {
                    float2 r2 = *(const float2*)(res + gi);
                    v0 += r2.x; v1 += r2.y;
                }
                if (outF) {
                    float2 o2 = make_float2(v0, v1);
                    *(float2*)(outF + gi) = o2;
                }
                if (outH) {
                    __half h0, l0, h1, l1;
                    split_f16(v0, h0, l0);
                    split_f16(v1, h1, l1);
                    __half2 hh; hh.x = h0; hh.y = h1;
                    *(__half2*)(outH + gi) = hh;
                    if (outL) {
                        __half2 ll; ll.x = l0; ll.y = l1;
                        *(__half2*)(outL + gi) = ll;
                    }
                }
            }
        }
    }
}

// --------------------------- flash attention (fp16) -------------------------
#define FA_PAD 72
#define FS_Q  0u
#define FS_K  18432u            // 2 stages x 9216
#define FS_V  36864u            // 2 stages x 9216
#define FS_M  55296u            // 2 stages x 8192
#define FA_SMEM 71680u

__global__ void __launch_bounds__(256, 1) flash_attn(
    const __half* __restrict__ Qsrc, const __half* __restrict__ Ksrc,
    const __half* __restrict__ Vsrc,
    size_t qBatch, size_t kvBatch, int qStride, int kvStride,
    const unsigned char* __restrict__ maskp,
    __half* __restrict__ Oh, __half* __restrict__ Ol)
{
    extern __shared__ char smem[];
    uint32_t smb = smem_u32(smem);
    int tid = threadIdx.x;
    int wid = tid >> 5, lane = tid & 31;
    int wq = wid << 4;
    int bh = blockIdx.y;
    int b = bh / Hh, h = bh % Hh;
    int qrow0 = blockIdx.x * 128;

    const __half* Qb = Qsrc + (size_t)b * qBatch + h * HD;
    const __half* Kb = Ksrc + (size_t)b * kvBatch + h * HD;
    const __half* Vb = Vsrc + (size_t)b * kvBatch + h * HD;

    auto load_kv = [&](int t, int s) {
        #pragma unroll
        for (int j2 = 0; j2 < 2; j2++) {
            int idx = tid + j2 * 256;
            int r = idx >> 3, c = (idx & 7) << 3;
            cp16(smb + FS_K + s * 9216u + (uint32_t)(r * FA_PAD + c) * 2,
                 Kb + (size_t)(t * 64 + r) * kvStride + c);
            cp16(smb + FS_V + s * 9216u + (uint32_t)(r * FA_PAD + c) * 2,
                 Vb + (size_t)(t * 64 + r) * kvStride + c);
        }
        if (maskp) {
            #pragma unroll
            for (int j2 = 0; j2 < 2; j2++) {
                int idx = tid + j2 * 256;
                int r = idx >> 2, c = (idx & 3) << 4;
                cp16(smb + FS_M + s * 8192u + (uint32_t)(r * 64 + c),
                     maskp + (size_t)(qrow0 + r) * NKk + t * 64 + c);
            }
        }
    };

    #pragma unroll
    for (int j4 = 0; j4 < 4; j4++) {
        int idx = tid + j4 * 256;
        int r = idx >> 3, c = (idx & 7) << 3;
        cp16(smb + FS_Q + (uint32_t)(r * FA_PAD + c) * 2,
             Qb + (size_t)(qrow0 + r) * qStride + c);
    }
    load_kv(0, 0);
    CP_COMMIT();

    uint32_t Aq[4][4];
    float O[8][4];
    #pragma unroll
    for (int j = 0; j < 8; j++)
        #pragma unroll
        for (int e = 0; e < 4; e++) O[j][e] = 0.f;
    float m0 = -1e30f, m1 = -1e30f, l0 = 0.f, l1 = 0.f;

    int r0l = wq + (lane >> 2);
    int cb2 = (lane & 3) * 2;

    for (int t = 0; t < 16; t++) {
        int s = t & 1;
        if (t + 1 < 16) {
            load_kv(t + 1, s ^ 1);
            CP_COMMIT();
            CP_WAIT(1);
        } else {
            CP_WAIT(0);
        }
        __syncthreads();

        if (t == 0) {
            #pragma unroll
            for (int kc = 0; kc < 4; kc++) {
                uint32_t off = (uint32_t)((wq + (lane & 15)) * FA_PAD
                               + kc * 16 + ((lane >> 4) << 3)) * 2;
                ldm_x4(Aq[kc], smb + FS_Q + off);
            }
        }

        float S[8][4];
        #pragma unroll
        for (int j = 0; j < 8; j++)
            #pragma unroll
            for (int e = 0; e < 4; e++) S[j][e] = 0.f;
        uint32_t sK = smb + FS_K + s * 9216u;
        #pragma unroll
        for (int kc = 0; kc < 4; kc++) {
            #pragma unroll
            for (int j = 0; j < 8; j++) {
                uint32_t bk[2];
                uint32_t off = (uint32_t)((8 * j + (lane & 7)) * FA_PAD
                               + 16 * kc + ((lane >> 3) & 1) * 8) * 2;
                ldm_x2(bk, sK + off);
                mma_f16(S[j], Aq[kc], bk);
            }
        }

        const unsigned char* sM = (const unsigned char*)(smem + FS_M + s * 8192u);
        #pragma unroll
        for (int j = 0; j < 8; j++) {
            S[j][0] *= SCALE; S[j][1] *= SCALE;
            S[j][2] *= SCALE; S[j][3] *= SCALE;
            if (maskp) {
                int col = 8 * j + cb2;
                unsigned short mw0 = *(const unsigned short*)(sM + r0l * 64 + col);
                unsigned short mw1 = *(const unsigned short*)(sM + (r0l + 8) * 64 + col);
                if (!(mw0 & 0xFF))   S[j][0] = -1e9f;
                if (!(mw0 >> 8))     S[j][1] = -1e9f;
                if (!(mw1 & 0xFF))   S[j][2] = -1e9f;
                if (!(mw1 >> 8))     S[j][3] = -1e9f;
            }
        }

        float mx0 = -1e30f, mx1 = -1e30f;
        #pragma unroll
        for (int j = 0; j < 8; j++) {
            mx0 = fmaxf(mx0, fmaxf(S[j][0], S[j][1]));
            mx1 = fmaxf(mx1, fmaxf(S[j][2], S[j][3]));
        }
        mx0 = fmaxf(mx0, __shfl_xor_sync(0xffffffffu, mx0, 1));
        mx0 = fmaxf(mx0, __shfl_xor_sync(0xffffffffu, mx0, 2));
        mx1 = fmaxf(mx1, __shfl_xor_sync(0xffffffffu, mx1, 1));
        mx1 = fmaxf(mx1, __shfl_xor_sync(0xffffffffu, mx1, 2));
        float mn0 = fmaxf(m0, mx0), mn1 = fmaxf(m1, mx1);
        float a0 = __expf(m0 - mn0), a1 = __expf(m1 - mn1);
        float sum0 = 0.f, sum1 = 0.f;
        #pragma unroll
        for (int j = 0; j < 8; j++) {
            S[j][0] = __expf(S[j][0] - mn0); sum0 += S[j][0];
            S[j][1] = __expf(S[j][1] - mn0); sum0 += S[j][1];
            S[j][2] = __expf(S[j][2] - mn1); sum1 += S[j][2];
            S[j][3] = __expf(S[j][3] - mn1); sum1 += S[j][3];
        }
        l0 = l0 * a0 + sum0;
        l1 = l1 * a1 + sum1;
        m0 = mn0; m1 = mn1;
        #pragma unroll
        for (int j = 0; j < 8; j++) {
            O[j][0] *= a0; O[j][1] *= a0;
            O[j][2] *= a1; O[j][3] *= a1;
        }

        uint32_t sV = smb + FS_V + s * 9216u;
        #pragma unroll
        for (int kc = 0; kc < 4; kc++) {
            uint32_t Ap[4];
            Ap[0] = packh(S[2 * kc][0],     S[2 * kc][1]);
            Ap[1] = packh(S[2 * kc][2],     S[2 * kc][3]);
            Ap[2] = packh(S[2 * kc + 1][0], S[2 * kc + 1][1]);
            Ap[3] = packh(S[2 * kc + 1][2], S[2 * kc + 1][3]);
            #pragma unroll
            for (int j = 0; j < 8; j++) {
                uint32_t bv[2];
                uint32_t off = (uint32_t)((16 * kc + (lane & 15)) * FA_PAD + 8 * j) * 2;
                ldm_x2t(bv, sV + off);
                mma_f16(O[j], Ap, bv);
            }
        }
        __syncthreads();
    }

    l0 += __shfl_xor_sync(0xffffffffu, l0, 1);
    l0 += __shfl_xor_sync(0xffffffffu, l0, 2);
    l1 += __shfl_xor_sync(0xffffffffu, l1, 1);
    l1 += __shfl_xor_sync(0xffffffffu, l1, 2);
    float inv0 = 1.f / l0, inv1 = 1.f / l1;
    int grow0 = qrow0 + r0l;
    size_t obase = (size_t)b * NQ * Cc + (size_t)h * HD;
    #pragma unroll
    for (int j = 0; j < 8; j++) {
        int col = 8 * j + cb2;
        float v0 = O[j][0] * inv0, v1 = O[j][1] * inv0;
        float v2 = O[j][2] * inv1, v3 = O[j][3] * inv1;
        __half h0, l0b, h1, l1b;
        size_t gi0 = obase + (size_t)grow0 * Cc + col;
        split_f16(v0, h0, l0b); split_f16(v1, h1, l1b);
        { __half2 hh; hh.x = h0; hh.y = h1; *(__half2*)(Oh + gi0) = hh; }
        { __half2 ll; ll.x = l0b; ll.y = l1b; *(__half2*)(Ol + gi0) = ll; }
        size_t gi1 = obase + (size_t)(grow0 + 8) * Cc + col;
        split_f16(v2, h0, l0b); split_f16(v3, h1, l1b);
        { __half2 hh; hh.x = h0; hh.y = h1; *(__half2*)(Oh + gi1) = hh; }
        { __half2 ll; ll.x = l0b; ll.y = l1b; *(__half2*)(Ol + gi1) = ll; }
    }
}

// ------------------------------ copy (y) -----------------------------------
__global__ void copy4_kernel(const float4* __restrict__ src, float4* __restrict__ dst, int n4)
{
    int i = blockIdx.x * blockDim.x + threadIdx.x;
    if (i < n4) dst[i] = src[i];
}

// ----------------------------- launch --------------------------------------
extern "C" void kernel_launch(void* const* d_in, const int* in_sizes, int n_in,
                              void* d_out, int out_size)
{
    const float* x        = (const float*)d_in[0];
    const float* y        = (const float*)d_in[1];
    const void*  mask_raw = d_in[4];
    const float* qkv_w    = (const float*)d_in[5];
    const float* aproj_w  = (const float*)d_in[6];
    const float* aproj_b  = (const float*)d_in[7];
    const float* q_w      = (const float*)d_in[8];
    const float* k_w      = (const float*)d_in[9];
    const float* v_w      = (const float*)d_in[10];
    const float* cproj_w  = (const float*)d_in[11];
    const float* cproj_b  = (const float*)d_in[12];
    const float* fc1_w    = (const float*)d_in[13];
    const float* fc1_b    = (const float*)d_in[14];
    const float* fc2_w    = (const float*)d_in[15];
    const float* fc2_b    = (const float*)d_in[16];
    const float* ln1_g    = (const float*)d_in[17];
    const float* ln1_b    = (const float*)d_in[18];
    const float* ln2_g    = (const float*)d_in[19];
    const float* ln2_b    = (const float*)d_in[20];
    const float* ln3_g    = (const float*)d_in[21];
    const float* ln3_b    = (const float*)d_in[22];
    const float* lny_g    = (const float*)d_in[23];
    const float* lny_b    = (const float*)d_in[24];
    float* out = (float*)d_out;

    float *p_x1, *p_x2;
    __half *p_qkvh, *p_qh, *p_kvh;
    __half *p_lnh, *p_lnl, *p_ylnh, *p_ylnl, *p_aoh, *p_aol, *p_h1h, *p_h1l, *p_w;
    unsigned char* p_mask;
    cudaGetSymbolAddress((void**)&p_x1,  g_x1);
    cudaGetSymbolAddress((void**)&p_x2,  g_x2);
    cudaGetSymbolAddress((void**)&p_qkvh, g_qkvh);
    cudaGetSymbolAddress((void**)&p_qh,  g_qh);
    cudaGetSymbolAddress((void**)&p_kvh, g_kvh);
    cudaGetSymbolAddress((void**)&p_lnh, g_ln_hi);
    cudaGetSymbolAddress((void**)&p_lnl, g_ln_lo);
    cudaGetSymbolAddress((void**)&p_ylnh, g_yln_hi);
    cudaGetSymbolAddress((void**)&p_ylnl, g_yln_lo);
    cudaGetSymbolAddress((void**)&p_aoh, g_ao_hi);
    cudaGetSymbolAddress((void**)&p_aol, g_ao_lo);
    cudaGetSymbolAddress((void**)&p_h1h, g_h1_hi);
    cudaGetSymbolAddress((void**)&p_h1l, g_h1_lo);
    cudaGetSymbolAddress((void**)&p_w,   g_w);
    cudaGetSymbolAddress((void**)&p_mask, g_mask);

    cudaFuncSetAttribute(gemm_tc, cudaFuncAttributeMaxDynamicSharedMemorySize, GSM_TOTAL);
    cudaFuncSetAttribute(flash_attn, cudaFuncAttributeMaxDynamicSharedMemorySize, FA_SMEM);

    dim3 t256(256);
    dim3 gFlash(NQ / 128, Bb * Hh);

    // launch 0: weight conversion (single kernel)
    wconvert_all<<<(W_TOT + 255) / 256, t256>>>(
        qkv_w, aproj_w, q_w, k_w, v_w, cproj_w, fc1_w, fc2_w);
    // launches 1-2: mask
    mask_detect<<<1, 256>>>((const unsigned int*)mask_raw);
    mask_decode<<<(NQ * NKk + 255) / 256, t256>>>(mask_raw);
    // launches 3-4: LNs
    ln_kernel<<<MROWS, t256>>>(x, ln1_g, ln1_b, p_lnh, p_lnl);
    ln_kernel<<<MROWS, t256>>>(y, lny_g, lny_b, p_ylnh, p_ylnl);

    // launch 5 (ncu sample target): qkv GEMM
    gemm_tc<<<dim3(3 * Cc / 128, MROWS / 128), t256, GSM_TOTAL>>>(
        p_lnh, p_lnl, p_w + W_QKV, Cc, 3 * Cc,
        nullptr, nullptr, 0, nullptr, p_qkvh, nullptr);
    flash_attn<<<gFlash, t256, FA_SMEM>>>(
        p_qkvh, p_qkvh + Cc, p_qkvh + 2 * Cc,
        (size_t)NQ * 3 * Cc, (size_t)NQ * 3 * Cc, 3 * Cc, 3 * Cc,
        nullptr, p_aoh, p_aol);
    gemm_tc<<<dim3(Cc / 128, MROWS / 128), t256, GSM_TOTAL>>>(
        p_aoh, p_aol, p_w + W_APROJ, Cc, Cc,
        aproj_b, x, 0, p_x1, nullptr, nullptr);

    // ---- cross attention ----
    ln_kernel<<<MROWS, t256>>>(p_x1, ln2_g, ln2_b, p_lnh, p_lnl);
    gemm_tc<<<dim3(Cc / 128, MROWS / 128), t256, GSM_TOTAL>>>(
        p_lnh, p_lnl, p_w + W_Q, Cc, Cc,
        nullptr, nullptr, 0, nullptr, p_qh, nullptr);
    gemm_tc<<<dim3(2 * Cc / 128, MROWS / 128), t256, GSM_TOTAL>>>(
        p_ylnh, p_ylnl, p_w + W_K, Cc, 2 * Cc,
        nullptr, nullptr, 0, nullptr, p_kvh, nullptr);
    flash_attn<<<gFlash, t256, FA_SMEM>>>(
        p_qh, p_kvh, p_kvh + Cc,
        (size_t)NQ * Cc, (size_t)NKk * 2 * Cc, Cc, 2 * Cc,
        p_mask, p_aoh, p_aol);
    gemm_tc<<<dim3(Cc / 128, MROWS / 128), t256, GSM_TOTAL>>>(
        p_aoh, p_aol, p_w + W_CPROJ, Cc, Cc,
        cproj_b, p_x1, 0, p_x2, nullptr, nullptr);

    // ---- MLP ----
    ln_kernel<<<MROWS, t256>>>(p_x2, ln3_g, ln3_b, p_lnh, p_lnl);
    gemm_tc<<<dim3(HID / 128, MROWS / 128), t256, GSM_TOTAL>>>(
        p_lnh, p_lnl, p_w + W_FC1, Cc, HID,
        fc1_b, nullptr, 1, nullptr, p_h1h, p_h1l);
    gemm_tc<<<dim3(Cc / 128, MROWS / 128), t256, GSM_TOTAL>>>(
        p_h1h, p_h1l, p_w + W_FC2, HID, Cc,
        fc2_b, p_x2, 0, out, nullptr, nullptr);

    // ---- y passthrough ----
    int n4 = (MROWS * Cc) / 4;
    copy4_kernel<<<(n4 + 255) / 256, t256>>>((const float4*)y,
        (float4*)(out + (size_t)MROWS * Cc), n4);
}

// round 7
// speedup vs baseline: 6.2698x; 1.5792x over previous
#include <cuda_runtime.h>
#include <cuda_fp16.h>
#include <math.h>
#include <stdint.h>

// ---------------------------------------------------------------------------
// DinoDecoderBlock: B=8, NQ=NK=1024, C=768, H=12, HD=64, HID=3072
// Round 7: plain fp16 GEMMs (A and W both single fp16; error = A+W rounding
// ~2-3e-4, under 1e-3). 2 CTAs/SM on the GEMM. Flash attention fp16.
// ---------------------------------------------------------------------------

#define Bb   8
#define NQ   1024
#define NKk  1024
#define Cc   768
#define Hh   12
#define HD   64
#define HID  3072
#define MROWS (Bb*NQ)          // 8192
#define SCALE 0.125f

// ------------------------- scratch (no allocs allowed) ---------------------
__device__ float g_x1   [(size_t)MROWS*Cc];
__device__ float g_x2   [(size_t)MROWS*Cc];

__device__ __half g_qkvh [(size_t)MROWS*3*Cc];   // self-attn QKV fp16
__device__ __half g_qh   [(size_t)MROWS*Cc];     // cross Q fp16
__device__ __half g_kvh  [(size_t)MROWS*2*Cc];   // cross K|V fp16 (merged)

__device__ __half g_ln  [(size_t)MROWS*Cc];
__device__ __half g_yln [(size_t)MROWS*Cc];
__device__ __half g_ao  [(size_t)MROWS*Cc];
__device__ __half g_h1  [(size_t)MROWS*HID];

// all weights concatenated (single fp16)
#define W_QKV   0u
#define W_APROJ 1769472u
#define W_Q     2359296u
#define W_K     2949120u
#define W_V     3538944u
#define W_CPROJ 4128768u
#define W_FC1   4718592u
#define W_FC2   7077888u
#define W_TOT   9437184u
__device__ __half g_w[W_TOT];

__device__ unsigned char g_mask[(size_t)NQ*NKk];
__device__ int g_mask_is_u8;

// --------------------------- PTX helpers -----------------------------------
__device__ __forceinline__ uint32_t smem_u32(const void* p) {
    uint32_t a;
    asm("{ .reg .u64 t; cvta.to.shared.u64 t, %1; cvt.u32.u64 %0, t; }"
        : "=r"(a) : "l"(p));
    return a;
}
__device__ __forceinline__ void cp16(uint32_t dst, const void* src) {
    asm volatile("cp.async.cg.shared.global [%0], [%1], 16;" :: "r"(dst), "l"(src));
}
#define CP_COMMIT() asm volatile("cp.async.commit_group;" ::: "memory")
#define CP_WAIT(n)  asm volatile("cp.async.wait_group %0;" :: "n"(n) : "memory")

__device__ __forceinline__ void ldm_x4(uint32_t* r, uint32_t addr) {
    asm volatile("ldmatrix.sync.aligned.m8n8.x4.shared.b16 {%0,%1,%2,%3}, [%4];"
                 : "=r"(r[0]), "=r"(r[1]), "=r"(r[2]), "=r"(r[3]) : "r"(addr));
}
__device__ __forceinline__ void ldm_x2(uint32_t* r, uint32_t addr) {
    asm volatile("ldmatrix.sync.aligned.m8n8.x2.shared.b16 {%0,%1}, [%2];"
                 : "=r"(r[0]), "=r"(r[1]) : "r"(addr));
}
__device__ __forceinline__ void ldm_x2t(uint32_t* r, uint32_t addr) {
    asm volatile("ldmatrix.sync.aligned.m8n8.x2.trans.shared.b16 {%0,%1}, [%2];"
                 : "=r"(r[0]), "=r"(r[1]) : "r"(addr));
}
__device__ __forceinline__ void mma_f16(float* d, const uint32_t* a, const uint32_t* b) {
    asm volatile(
        "mma.sync.aligned.m16n8k16.row.col.f32.f16.f16.f32 "
        "{%0,%1,%2,%3}, {%4,%5,%6,%7}, {%8,%9}, {%0,%1,%2,%3};"
        : "+f"(d[0]), "+f"(d[1]), "+f"(d[2]), "+f"(d[3])
        : "r"(a[0]), "r"(a[1]), "r"(a[2]), "r"(a[3]), "r"(b[0]), "r"(b[1]));
}
__device__ __forceinline__ uint32_t packh(float a, float b) {
    __half2 t = __floats2half2_rn(a, b);
    return *(uint32_t*)&t;
}

// --------------------------- weight convert (one kernel) -------------------
__global__ void wconvert_all(
    const float* __restrict__ s0, const float* __restrict__ s1,
    const float* __restrict__ s2, const float* __restrict__ s3,
    const float* __restrict__ s4, const float* __restrict__ s5,
    const float* __restrict__ s6, const float* __restrict__ s7)
{
    unsigned int i = blockIdx.x * blockDim.x + threadIdx.x;
    if (i >= W_TOT) return;
    float v;
    if      (i < W_APROJ) v = s0[i - W_QKV];
    else if (i < W_Q)     v = s1[i - W_APROJ];
    else if (i < W_K)     v = s2[i - W_Q];
    else if (i < W_V)     v = s3[i - W_K];
    else if (i < W_CPROJ) v = s4[i - W_V];
    else if (i < W_FC1)   v = s5[i - W_CPROJ];
    else if (i < W_FC2)   v = s6[i - W_FC1];
    else                  v = s7[i - W_FC2];
    g_w[i] = __float2half_rn(v);
}

// --------------------------- mask detect/decode ----------------------------
__global__ void mask_detect(const unsigned int* __restrict__ m)
{
    __shared__ int flag;
    if (threadIdx.x == 0) flag = 0;
    __syncthreads();
    for (int i = threadIdx.x; i < 65536; i += blockDim.x)
        if (m[i] > 1u) flag = 1;
    __syncthreads();
    if (threadIdx.x == 0) g_mask_is_u8 = flag;
}
__global__ void mask_decode(const void* __restrict__ msrc)
{
    size_t i = (size_t)blockIdx.x * blockDim.x + threadIdx.x;
    if (i >= (size_t)NQ * NKk) return;
    unsigned char v;
    if (g_mask_is_u8) v = ((const unsigned char*)msrc)[i] ? 1 : 0;
    else              v = ((const int*)msrc)[i] ? 1 : 0;
    g_mask[i] = v;
}

// ------------------------------ LayerNorm ----------------------------------
__global__ void ln_kernel(const float* __restrict__ X, const float* __restrict__ g,
                          const float* __restrict__ b, __half* __restrict__ O)
{
    int row = blockIdx.x;
    const float* x = X + (size_t)row * Cc;
    int t = threadIdx.x;
    float v0 = x[t], v1 = x[t + 256], v2 = x[t + 512];
    float s  = v0 + v1 + v2;
    float s2 = v0*v0 + v1*v1 + v2*v2;
    #pragma unroll
    for (int off = 16; off; off >>= 1) {
        s  += __shfl_xor_sync(0xffffffffu, s,  off);
        s2 += __shfl_xor_sync(0xffffffffu, s2, off);
    }
    __shared__ float shs[8], shs2[8];
    int w = t >> 5, l = t & 31;
    if (l == 0) { shs[w] = s; shs2[w] = s2; }
    __syncthreads();
    if (w == 0) {
        s  = (l < 8) ? shs[l]  : 0.f;
        s2 = (l < 8) ? shs2[l] : 0.f;
        #pragma unroll
        for (int off = 4; off; off >>= 1) {
            s  += __shfl_xor_sync(0xffffffffu, s,  off);
            s2 += __shfl_xor_sync(0xffffffffu, s2, off);
        }
        if (l == 0) { shs[0] = s; shs2[0] = s2; }
    }
    __syncthreads();
    float mean = shs[0] * (1.f / Cc);
    float var  = shs2[0] * (1.f / Cc) - mean * mean;
    float inv  = rsqrtf(var + 1e-5f);
    size_t base = (size_t)row * Cc;
    #pragma unroll
    for (int j = 0; j < 3; j++) {
        int c = t + j * 256;
        float v = (j == 0 ? v0 : (j == 1 ? v1 : v2));
        O[base + c] = __float2half_rn((v - mean) * inv * g[c] + b[c]);
    }
}

// --------------------------- HMMA GEMM (fp16) ------------------------------
// C[M,N] = A[M,K] @ W[N,K]^T + epilogue. 256 threads, 128x128, BK=32,
// 2-stage cp.async, 2 CTAs/SM.
#define PADR 40
#define TILE_B (128 * PADR * 2)       // 10240 bytes
#define STAGE_B (2 * TILE_B)          // 20480 bytes
#define GSM_TOTAL (2 * STAGE_B)       // 40960 bytes

__global__ void __launch_bounds__(256, 2) gemm_tc(
    const __half* __restrict__ Ah, const __half* __restrict__ Bw,
    int K, int N,
    const float* __restrict__ bias, const float* __restrict__ res, int gelu,
    float* __restrict__ outF, __half* __restrict__ outH)
{
    extern __shared__ char smem[];
    uint32_t smb = smem_u32(smem);
    int tid = threadIdx.x;
    int wid = tid >> 5, lane = tid & 31;
    int wm = wid >> 2, wn = wid & 3;            // warp tile: 64x32
    int m0 = blockIdx.y * 128;
    int n0 = blockIdx.x * 128;

    int lr0 = tid >> 2;
    int lc  = (tid & 3) << 3;

    float acc[4][4][4];
    #pragma unroll
    for (int i = 0; i < 4; i++)
        #pragma unroll
        for (int j = 0; j < 4; j++)
            #pragma unroll
            for (int r = 0; r < 4; r++) acc[i][j][r] = 0.f;

    int NIT = K >> 5;

    auto load_stage = [&](int it, int s) {
        int k0 = it << 5;
        uint32_t sb = smb + s * STAGE_B;
        #pragma unroll
        for (int tgt = 0; tgt < 2; tgt++) {
            const __half* base = (tgt == 0 ? Ah + (size_t)m0 * K
                                           : Bw + (size_t)n0 * K) + k0;
            uint32_t tb = sb + tgt * TILE_B;
            #pragma unroll
            for (int q = 0; q < 2; q++) {
                int row = lr0 + q * 64;
                cp16(tb + (uint32_t)(row * PADR + lc) * 2,
                     base + (size_t)row * K + lc);
            }
        }
    };

    load_stage(0, 0);
    CP_COMMIT();

    for (int it = 0; it < NIT; it++) {
        int s = it & 1;
        if (it + 1 < NIT) {
            load_stage(it + 1, s ^ 1);
            CP_COMMIT();
            CP_WAIT(1);
        } else {
            CP_WAIT(0);
        }
        __syncthreads();

        uint32_t sA = smb + s * STAGE_B;
        uint32_t sB = sA + TILE_B;

        #pragma unroll
        for (int kk = 0; kk < 32; kk += 16) {
            uint32_t ah[4][4], bw[4][2];
            int arow = lane & 15;
            int acol = kk + ((lane >> 4) << 3);
            #pragma unroll
            for (int i = 0; i < 4; i++) {
                uint32_t off = (uint32_t)((wm * 64 + i * 16 + arow) * PADR + acol) * 2;
                ldm_x4(ah[i], sA + off);
            }
            int brow = lane & 7;
            int bcol = kk + ((lane >> 3) & 1) * 8;
            #pragma unroll
            for (int j = 0; j < 4; j++) {
                uint32_t off = (uint32_t)((wn * 32 + j * 8 + brow) * PADR + bcol) * 2;
                ldm_x2(bw[j], sB + off);
            }
            #pragma unroll
            for (int i = 0; i < 4; i++)
                #pragma unroll
                for (int j = 0; j < 4; j++)
                    mma_f16(acc[i][j], ah[i], bw[j]);
        }
        __syncthreads();
    }

    #pragma unroll
    for (int i = 0; i < 4; i++) {
        #pragma unroll
        for (int j = 0; j < 4; j++) {
            int mb = m0 + wm * 64 + i * 16 + (lane >> 2);
            int nb = n0 + wn * 32 + j * 8 + (lane & 3) * 2;
            #pragma unroll
            for (int half = 0; half < 2; half++) {
                int m = mb + half * 8;
                float v0 = acc[i][j][half * 2 + 0];
                float v1 = acc[i][j][half * 2 + 1];
                if (bias) { v0 += bias[nb]; v1 += bias[nb + 1]; }
                if (gelu) {
                    v0 = 0.5f * v0 * (1.0f + erff(v0 * 0.70710678118654752f));
                    v1 = 0.5f * v1 * (1.0f + erff(v1 * 0.70710678118654752f));
                }
                size_t gi = (size_t)m * N + nb;
                if (res) {
                    float2 r2 = *(const float2*)(res + gi);
                    v0 += r2.x; v1 += r2.y;
                }
                if (outF) {
                    float2 o2 = make_float2(v0, v1);
                    *(float2*)(outF + gi) = o2;
                }
                if (outH) {
                    __half2 hh = __floats2half2_rn(v0, v1);
                    *(__half2*)(outH + gi) = hh;
                }
            }
        }
    }
}

// --------------------------- flash attention (fp16) -------------------------
#define FA_PAD 72
#define FS_Q  0u
#define FS_K  18432u            // 2 stages x 9216
#define FS_V  36864u            // 2 stages x 9216
#define FS_M  55296u            // 2 stages x 8192
#define FA_SMEM 71680u

__global__ void __launch_bounds__(256, 1) flash_attn(
    const __half* __restrict__ Qsrc, const __half* __restrict__ Ksrc,
    const __half* __restrict__ Vsrc,
    size_t qBatch, size_t kvBatch, int qStride, int kvStride,
    const unsigned char* __restrict__ maskp,
    __half* __restrict__ Oh)
{
    extern __shared__ char smem[];
    uint32_t smb = smem_u32(smem);
    int tid = threadIdx.x;
    int wid = tid >> 5, lane = tid & 31;
    int wq = wid << 4;
    int bh = blockIdx.y;
    int b = bh / Hh, h = bh % Hh;
    int qrow0 = blockIdx.x * 128;

    const __half* Qb = Qsrc + (size_t)b * qBatch + h * HD;
    const __half* Kb = Ksrc + (size_t)b * kvBatch + h * HD;
    const __half* Vb = Vsrc + (size_t)b * kvBatch + h * HD;

    auto load_kv = [&](int t, int s) {
        #pragma unroll
        for (int j2 = 0; j2 < 2; j2++) {
            int idx = tid + j2 * 256;
            int r = idx >> 3, c = (idx & 7) << 3;
            cp16(smb + FS_K + s * 9216u + (uint32_t)(r * FA_PAD + c) * 2,
                 Kb + (size_t)(t * 64 + r) * kvStride + c);
            cp16(smb + FS_V + s * 9216u + (uint32_t)(r * FA_PAD + c) * 2,
                 Vb + (size_t)(t * 64 + r) * kvStride + c);
        }
        if (maskp) {
            #pragma unroll
            for (int j2 = 0; j2 < 2; j2++) {
                int idx = tid + j2 * 256;
                int r = idx >> 2, c = (idx & 3) << 4;
                cp16(smb + FS_M + s * 8192u + (uint32_t)(r * 64 + c),
                     maskp + (size_t)(qrow0 + r) * NKk + t * 64 + c);
            }
        }
    };

    #pragma unroll
    for (int j4 = 0; j4 < 4; j4++) {
        int idx = tid + j4 * 256;
        int r = idx >> 3, c = (idx & 7) << 3;
        cp16(smb + FS_Q + (uint32_t)(r * FA_PAD + c) * 2,
             Qb + (size_t)(qrow0 + r) * qStride + c);
    }
    load_kv(0, 0);
    CP_COMMIT();

    uint32_t Aq[4][4];
    float O[8][4];
    #pragma unroll
    for (int j = 0; j < 8; j++)
        #pragma unroll
        for (int e = 0; e < 4; e++) O[j][e] = 0.f;
    float m0 = -1e30f, m1 = -1e30f, l0 = 0.f, l1 = 0.f;

    int r0l = wq + (lane >> 2);
    int cb2 = (lane & 3) * 2;

    for (int t = 0; t < 16; t++) {
        int s = t & 1;
        if (t + 1 < 16) {
            load_kv(t + 1, s ^ 1);
            CP_COMMIT();
            CP_WAIT(1);
        } else {
            CP_WAIT(0);
        }
        __syncthreads();

        if (t == 0) {
            #pragma unroll
            for (int kc = 0; kc < 4; kc++) {
                uint32_t off = (uint32_t)((wq + (lane & 15)) * FA_PAD
                               + kc * 16 + ((lane >> 4) << 3)) * 2;
                ldm_x4(Aq[kc], smb + FS_Q + off);
            }
        }

        float S[8][4];
        #pragma unroll
        for (int j = 0; j < 8; j++)
            #pragma unroll
            for (int e = 0; e < 4; e++) S[j][e] = 0.f;
        uint32_t sK = smb + FS_K + s * 9216u;
        #pragma unroll
        for (int kc = 0; kc < 4; kc++) {
            #pragma unroll
            for (int j = 0; j < 8; j++) {
                uint32_t bk[2];
                uint32_t off = (uint32_t)((8 * j + (lane & 7)) * FA_PAD
                               + 16 * kc + ((lane >> 3) & 1) * 8) * 2;
                ldm_x2(bk, sK + off);
                mma_f16(S[j], Aq[kc], bk);
            }
        }

        const unsigned char* sM = (const unsigned char*)(smem + FS_M + s * 8192u);
        #pragma unroll
        for (int j = 0; j < 8; j++) {
            S[j][0] *= SCALE; S[j][1] *= SCALE;
            S[j][2] *= SCALE; S[j][3] *= SCALE;
            if (maskp) {
                int col = 8 * j + cb2;
                unsigned short mw0 = *(const unsigned short*)(sM + r0l * 64 + col);
                unsigned short mw1 = *(const unsigned short*)(sM + (r0l + 8) * 64 + col);
                if (!(mw0 & 0xFF))   S[j][0] = -1e9f;
                if (!(mw0 >> 8))     S[j][1] = -1e9f;
                if (!(mw1 & 0xFF))   S[j][2] = -1e9f;
                if (!(mw1 >> 8))     S[j][3] = -1e9f;
            }
        }

        float mx0 = -1e30f, mx1 = -1e30f;
        #pragma unroll
        for (int j = 0; j < 8; j++) {
            mx0 = fmaxf(mx0, fmaxf(S[j][0], S[j][1]));
            mx1 = fmaxf(mx1, fmaxf(S[j][2], S[j][3]));
        }
        mx0 = fmaxf(mx0, __shfl_xor_sync(0xffffffffu, mx0, 1));
        mx0 = fmaxf(mx0, __shfl_xor_sync(0xffffffffu, mx0, 2));
        mx1 = fmaxf(mx1, __shfl_xor_sync(0xffffffffu, mx1, 1));
        mx1 = fmaxf(mx1, __shfl_xor_sync(0xffffffffu, mx1, 2));
        float mn0 = fmaxf(m0, mx0), mn1 = fmaxf(m1, mx1);
        float a0 = __expf(m0 - mn0), a1 = __expf(m1 - mn1);
        float sum0 = 0.f, sum1 = 0.f;
        #pragma unroll
        for (int j = 0; j < 8; j++) {
            S[j][0] = __expf(S[j][0] - mn0); sum0 += S[j][0];
            S[j][1] = __expf(S[j][1] - mn0); sum0 += S[j][1];
            S[j][2] = __expf(S[j][2] - mn1); sum1 += S[j][2];
            S[j][3] = __expf(S[j][3] - mn1); sum1 += S[j][3];
        }
        l0 = l0 * a0 + sum0;
        l1 = l1 * a1 + sum1;
        m0 = mn0; m1 = mn1;
        #pragma unroll
        for (int j = 0; j < 8; j++) {
            O[j][0] *= a0; O[j][1] *= a0;
            O[j][2] *= a1; O[j][3] *= a1;
        }

        uint32_t sV = smb + FS_V + s * 9216u;
        #pragma unroll
        for (int kc = 0; kc < 4; kc++) {
            uint32_t Ap[4];
            Ap[0] = packh(S[2 * kc][0],     S[2 * kc][1]);
            Ap[1] = packh(S[2 * kc][2],     S[2 * kc][3]);
            Ap[2] = packh(S[2 * kc + 1][0], S[2 * kc + 1][1]);
            Ap[3] = packh(S[2 * kc + 1][2], S[2 * kc + 1][3]);
            #pragma unroll
            for (int j = 0; j < 8; j++) {
                uint32_t bv[2];
                uint32_t off = (uint32_t)((16 * kc + (lane & 15)) * FA_PAD + 8 * j) * 2;
                ldm_x2t(bv, sV + off);
                mma_f16(O[j], Ap, bv);
            }
        }
        __syncthreads();
    }

    l0 += __shfl_xor_sync(0xffffffffu, l0, 1);
    l0 += __shfl_xor_sync(0xffffffffu, l0, 2);
    l1 += __shfl_xor_sync(0xffffffffu, l1, 1);
    l1 += __shfl_xor_sync(0xffffffffu, l1, 2);
    float inv0 = 1.f / l0, inv1 = 1.f / l1;
    int grow0 = qrow0 + r0l;
    size_t obase = (size_t)b * NQ * Cc + (size_t)h * HD;
    #pragma unroll
    for (int j = 0; j < 8; j++) {
        int col = 8 * j + cb2;
        size_t gi0 = obase + (size_t)grow0 * Cc + col;
        *(__half2*)(Oh + gi0) = __floats2half2_rn(O[j][0] * inv0, O[j][1] * inv0);
        size_t gi1 = obase + (size_t)(grow0 + 8) * Cc + col;
        *(__half2*)(Oh + gi1) = __floats2half2_rn(O[j][2] * inv1, O[j][3] * inv1);
    }
}

// ------------------------------ copy (y) -----------------------------------
__global__ void copy4_kernel(const float4* __restrict__ src, float4* __restrict__ dst, int n4)
{
    int i = blockIdx.x * blockDim.x + threadIdx.x;
    if (i < n4) dst[i] = src[i];
}

// ----------------------------- launch --------------------------------------
extern "C" void kernel_launch(void* const* d_in, const int* in_sizes, int n_in,
                              void* d_out, int out_size)
{
    const float* x        = (const float*)d_in[0];
    const float* y        = (const float*)d_in[1];
    const void*  mask_raw = d_in[4];
    const float* qkv_w    = (const float*)d_in[5];
    const float* aproj_w  = (const float*)d_in[6];
    const float* aproj_b  = (const float*)d_in[7];
    const float* q_w      = (const float*)d_in[8];
    const float* k_w      = (const float*)d_in[9];
    const float* v_w      = (const float*)d_in[10];
    const float* cproj_w  = (const float*)d_in[11];
    const float* cproj_b  = (const float*)d_in[12];
    const float* fc1_w    = (const float*)d_in[13];
    const float* fc1_b    = (const float*)d_in[14];
    const float* fc2_w    = (const float*)d_in[15];
    const float* fc2_b    = (const float*)d_in[16];
    const float* ln1_g    = (const float*)d_in[17];
    const float* ln1_b    = (const float*)d_in[18];
    const float* ln2_g    = (const float*)d_in[19];
    const float* ln2_b    = (const float*)d_in[20];
    const float* ln3_g    = (const float*)d_in[21];
    const float* ln3_b    = (const float*)d_in[22];
    const float* lny_g    = (const float*)d_in[23];
    const float* lny_b    = (const float*)d_in[24];
    float* out = (float*)d_out;

    float *p_x1, *p_x2;
    __half *p_qkvh, *p_qh, *p_kvh, *p_ln, *p_yln, *p_ao, *p_h1, *p_w;
    unsigned char* p_mask;
    cudaGetSymbolAddress((void**)&p_x1,  g_x1);
    cudaGetSymbolAddress((void**)&p_x2,  g_x2);
    cudaGetSymbolAddress((void**)&p_qkvh, g_qkvh);
    cudaGetSymbolAddress((void**)&p_qh,  g_qh);
    cudaGetSymbolAddress((void**)&p_kvh, g_kvh);
    cudaGetSymbolAddress((void**)&p_ln,  g_ln);
    cudaGetSymbolAddress((void**)&p_yln, g_yln);
    cudaGetSymbolAddress((void**)&p_ao,  g_ao);
    cudaGetSymbolAddress((void**)&p_h1,  g_h1);
    cudaGetSymbolAddress((void**)&p_w,   g_w);
    cudaGetSymbolAddress((void**)&p_mask, g_mask);

    cudaFuncSetAttribute(gemm_tc, cudaFuncAttributeMaxDynamicSharedMemorySize, GSM_TOTAL);
    cudaFuncSetAttribute(flash_attn, cudaFuncAttributeMaxDynamicSharedMemorySize, FA_SMEM);

    dim3 t256(256);
    dim3 gFlash(NQ / 128, Bb * Hh);

    wconvert_all<<<(W_TOT + 255) / 256, t256>>>(
        qkv_w, aproj_w, q_w, k_w, v_w, cproj_w, fc1_w, fc2_w);
    mask_detect<<<1, 256>>>((const unsigned int*)mask_raw);
    mask_decode<<<(NQ * NKk + 255) / 256, t256>>>(mask_raw);
    ln_kernel<<<MROWS, t256>>>(x, ln1_g, ln1_b, p_ln);
    ln_kernel<<<MROWS, t256>>>(y, lny_g, lny_b, p_yln);

    // ---- self attention ----
    gemm_tc<<<dim3(3 * Cc / 128, MROWS / 128), t256, GSM_TOTAL>>>(
        p_ln, p_w + W_QKV, Cc, 3 * Cc,
        nullptr, nullptr, 0, nullptr, p_qkvh);
    flash_attn<<<gFlash, t256, FA_SMEM>>>(
        p_qkvh, p_qkvh + Cc, p_qkvh + 2 * Cc,
        (size_t)NQ * 3 * Cc, (size_t)NQ * 3 * Cc, 3 * Cc, 3 * Cc,
        nullptr, p_ao);
    gemm_tc<<<dim3(Cc / 128, MROWS / 128), t256, GSM_TOTAL>>>(
        p_ao, p_w + W_APROJ, Cc, Cc,
        aproj_b, x, 0, p_x1, nullptr);

    // ---- cross attention ----
    ln_kernel<<<MROWS, t256>>>(p_x1, ln2_g, ln2_b, p_ln);
    gemm_tc<<<dim3(Cc / 128, MROWS / 128), t256, GSM_TOTAL>>>(
        p_ln, p_w + W_Q, Cc, Cc,
        nullptr, nullptr, 0, nullptr, p_qh);
    gemm_tc<<<dim3(2 * Cc / 128, MROWS / 128), t256, GSM_TOTAL>>>(
        p_yln, p_w + W_K, Cc, 2 * Cc,
        nullptr, nullptr, 0, nullptr, p_kvh);
    flash_attn<<<gFlash, t256, FA_SMEM>>>(
        p_qh, p_kvh, p_kvh + Cc,
        (size_t)NQ * Cc, (size_t)NKk * 2 * Cc, Cc, 2 * Cc,
        p_mask, p_ao);
    gemm_tc<<<dim3(Cc / 128, MROWS / 128), t256, GSM_TOTAL>>>(
        p_ao, p_w + W_CPROJ, Cc, Cc,
        cproj_b, p_x1, 0, p_x2, nullptr);

    // ---- MLP ----
    ln_kernel<<<MROWS, t256>>>(p_x2, ln3_g, ln3_b, p_ln);
    gemm_tc<<<dim3(HID / 128, MROWS / 128), t256, GSM_TOTAL>>>(
        p_ln, p_w + W_FC1, Cc, HID,
        fc1_b, nullptr, 1, nullptr, p_h1);
    gemm_tc<<<dim3(Cc / 128, MROWS / 128), t256, GSM_TOTAL>>>(
        p_h1, p_w + W_FC2, HID, Cc,
        fc2_b, p_x2, 0, out, nullptr);

    // ---- y passthrough ----
    int n4 = (MROWS * Cc) / 4;
    copy4_kernel<<<(n4 + 255) / 256, t256>>>((const float4*)y,
        (float4*)(out + (size_t)MROWS * Cc), n4);
}

// round 8
// speedup vs baseline: 7.0271x; 1.1208x over previous
#include <cuda_runtime.h>
#include <cuda_fp16.h>
#include <math.h>
#include <stdint.h>

// ---------------------------------------------------------------------------
// DinoDecoderBlock: B=8, NQ=NK=1024, C=768, H=12, HD=64, HID=3072
// Round 8: (1) dual-stream graph overlap of independent y-branch,
// (2) 3-stage cp.async GEMM pipeline, (3) flash_attn at 2 CTAs/SM.
// Numerics unchanged from R7 (plain fp16 GEMMs + fp16 flash attention).
// ---------------------------------------------------------------------------

#define Bb   8
#define NQ   1024
#define NKk  1024
#define Cc   768
#define Hh   12
#define HD   64
#define HID  3072
#define MROWS (Bb*NQ)          // 8192
#define SCALE 0.125f

// ------------------------- scratch (no allocs allowed) ---------------------
__device__ float g_x1   [(size_t)MROWS*Cc];
__device__ float g_x2   [(size_t)MROWS*Cc];

__device__ __half g_qkvh [(size_t)MROWS*3*Cc];   // self-attn QKV fp16
__device__ __half g_qh   [(size_t)MROWS*Cc];     // cross Q fp16
__device__ __half g_kvh  [(size_t)MROWS*2*Cc];   // cross K|V fp16 (merged)

__device__ __half g_ln  [(size_t)MROWS*Cc];
__device__ __half g_yln [(size_t)MROWS*Cc];
__device__ __half g_ao  [(size_t)MROWS*Cc];
__device__ __half g_h1  [(size_t)MROWS*HID];

// all weights concatenated (single fp16)
#define W_QKV   0u
#define W_APROJ 1769472u
#define W_Q     2359296u
#define W_K     2949120u
#define W_V     3538944u
#define W_CPROJ 4128768u
#define W_FC1   4718592u
#define W_FC2   7077888u
#define W_TOT   9437184u
__device__ __half g_w[W_TOT];

__device__ unsigned char g_mask[(size_t)NQ*NKk];
__device__ int g_mask_is_u8;

// --------------------------- PTX helpers -----------------------------------
__device__ __forceinline__ uint32_t smem_u32(const void* p) {
    uint32_t a;
    asm("{ .reg .u64 t; cvta.to.shared.u64 t, %1; cvt.u32.u64 %0, t; }"
        : "=r"(a) : "l"(p));
    return a;
}
__device__ __forceinline__ void cp16(uint32_t dst, const void* src) {
    asm volatile("cp.async.cg.shared.global [%0], [%1], 16;" :: "r"(dst), "l"(src));
}
#define CP_COMMIT() asm volatile("cp.async.commit_group;" ::: "memory")
#define CP_WAIT(n)  asm volatile("cp.async.wait_group %0;" :: "n"(n) : "memory")

__device__ __forceinline__ void ldm_x4(uint32_t* r, uint32_t addr) {
    asm volatile("ldmatrix.sync.aligned.m8n8.x4.shared.b16 {%0,%1,%2,%3}, [%4];"
                 : "=r"(r[0]), "=r"(r[1]), "=r"(r[2]), "=r"(r[3]) : "r"(addr));
}
__device__ __forceinline__ void ldm_x2(uint32_t* r, uint32_t addr) {
    asm volatile("ldmatrix.sync.aligned.m8n8.x2.shared.b16 {%0,%1}, [%2];"
                 : "=r"(r[0]), "=r"(r[1]) : "r"(addr));
}
__device__ __forceinline__ void ldm_x2t(uint32_t* r, uint32_t addr) {
    asm volatile("ldmatrix.sync.aligned.m8n8.x2.trans.shared.b16 {%0,%1}, [%2];"
                 : "=r"(r[0]), "=r"(r[1]) : "r"(addr));
}
__device__ __forceinline__ void mma_f16(float* d, const uint32_t* a, const uint32_t* b) {
    asm volatile(
        "mma.sync.aligned.m16n8k16.row.col.f32.f16.f16.f32 "
        "{%0,%1,%2,%3}, {%4,%5,%6,%7}, {%8,%9}, {%0,%1,%2,%3};"
        : "+f"(d[0]), "+f"(d[1]), "+f"(d[2]), "+f"(d[3])
        : "r"(a[0]), "r"(a[1]), "r"(a[2]), "r"(a[3]), "r"(b[0]), "r"(b[1]));
}
__device__ __forceinline__ uint32_t packh(float a, float b) {
    __half2 t = __floats2half2_rn(a, b);
    return *(uint32_t*)&t;
}

// --------------------------- weight convert (one kernel) -------------------
__global__ void wconvert_all(
    const float* __restrict__ s0, const float* __restrict__ s1,
    const float* __restrict__ s2, const float* __restrict__ s3,
    const float* __restrict__ s4, const float* __restrict__ s5,
    const float* __restrict__ s6, const float* __restrict__ s7)
{
    unsigned int i = blockIdx.x * blockDim.x + threadIdx.x;
    if (i >= W_TOT) return;
    float v;
    if      (i < W_APROJ) v = s0[i - W_QKV];
    else if (i < W_Q)     v = s1[i - W_APROJ];
    else if (i < W_K)     v = s2[i - W_Q];
    else if (i < W_V)     v = s3[i - W_K];
    else if (i < W_CPROJ) v = s4[i - W_V];
    else if (i < W_FC1)   v = s5[i - W_CPROJ];
    else if (i < W_FC2)   v = s6[i - W_FC1];
    else                  v = s7[i - W_FC2];
    g_w[i] = __float2half_rn(v);
}

// --------------------------- mask detect/decode ----------------------------
__global__ void mask_detect(const unsigned int* __restrict__ m)
{
    __shared__ int flag;
    if (threadIdx.x == 0) flag = 0;
    __syncthreads();
    for (int i = threadIdx.x; i < 65536; i += blockDim.x)
        if (m[i] > 1u) flag = 1;
    __syncthreads();
    if (threadIdx.x == 0) g_mask_is_u8 = flag;
}
__global__ void mask_decode(const void* __restrict__ msrc)
{
    size_t i = (size_t)blockIdx.x * blockDim.x + threadIdx.x;
    if (i >= (size_t)NQ * NKk) return;
    unsigned char v;
    if (g_mask_is_u8) v = ((const unsigned char*)msrc)[i] ? 1 : 0;
    else              v = ((const int*)msrc)[i] ? 1 : 0;
    g_mask[i] = v;
}

// ------------------------------ LayerNorm ----------------------------------
__global__ void ln_kernel(const float* __restrict__ X, const float* __restrict__ g,
                          const float* __restrict__ b, __half* __restrict__ O)
{
    int row = blockIdx.x;
    const float* x = X + (size_t)row * Cc;
    int t = threadIdx.x;
    float v0 = x[t], v1 = x[t + 256], v2 = x[t + 512];
    float s  = v0 + v1 + v2;
    float s2 = v0*v0 + v1*v1 + v2*v2;
    #pragma unroll
    for (int off = 16; off; off >>= 1) {
        s  += __shfl_xor_sync(0xffffffffu, s,  off);
        s2 += __shfl_xor_sync(0xffffffffu, s2, off);
    }
    __shared__ float shs[8], shs2[8];
    int w = t >> 5, l = t & 31;
    if (l == 0) { shs[w] = s; shs2[w] = s2; }
    __syncthreads();
    if (w == 0) {
        s  = (l < 8) ? shs[l]  : 0.f;
        s2 = (l < 8) ? shs2[l] : 0.f;
        #pragma unroll
        for (int off = 4; off; off >>= 1) {
            s  += __shfl_xor_sync(0xffffffffu, s,  off);
            s2 += __shfl_xor_sync(0xffffffffu, s2, off);
        }
        if (l == 0) { shs[0] = s; shs2[0] = s2; }
    }
    __syncthreads();
    float mean = shs[0] * (1.f / Cc);
    float var  = shs2[0] * (1.f / Cc) - mean * mean;
    float inv  = rsqrtf(var + 1e-5f);
    size_t base = (size_t)row * Cc;
    #pragma unroll
    for (int j = 0; j < 3; j++) {
        int c = t + j * 256;
        float v = (j == 0 ? v0 : (j == 1 ? v1 : v2));
        O[base + c] = __float2half_rn((v - mean) * inv * g[c] + b[c]);
    }
}

// --------------------------- HMMA GEMM (fp16, 3-stage) ---------------------
// C[M,N] = A[M,K] @ W[N,K]^T + epilogue. 256 threads, 128x128, BK=32,
// 3-stage cp.async, 2 CTAs/SM.
#define PADR 40
#define TILE_B (128 * PADR * 2)       // 10240 bytes
#define STAGE_B (2 * TILE_B)          // 20480 bytes
#define GSM_TOTAL (3 * STAGE_B)       // 61440 bytes

__global__ void __launch_bounds__(256, 2) gemm_tc(
    const __half* __restrict__ Ah, const __half* __restrict__ Bw,
    int K, int N,
    const float* __restrict__ bias, const float* __restrict__ res, int gelu,
    float* __restrict__ outF, __half* __restrict__ outH)
{
    extern __shared__ char smem[];
    uint32_t smb = smem_u32(smem);
    int tid = threadIdx.x;
    int wid = tid >> 5, lane = tid & 31;
    int wm = wid >> 2, wn = wid & 3;            // warp tile: 64x32
    int m0 = blockIdx.y * 128;
    int n0 = blockIdx.x * 128;

    int lr0 = tid >> 2;
    int lc  = (tid & 3) << 3;

    float acc[4][4][4];
    #pragma unroll
    for (int i = 0; i < 4; i++)
        #pragma unroll
        for (int j = 0; j < 4; j++)
            #pragma unroll
            for (int r = 0; r < 4; r++) acc[i][j][r] = 0.f;

    int NIT = K >> 5;

    auto load_stage = [&](int it, int s) {
        int k0 = it << 5;
        uint32_t sb = smb + s * STAGE_B;
        #pragma unroll
        for (int tgt = 0; tgt < 2; tgt++) {
            const __half* base = (tgt == 0 ? Ah + (size_t)m0 * K
                                           : Bw + (size_t)n0 * K) + k0;
            uint32_t tb = sb + tgt * TILE_B;
            #pragma unroll
            for (int q = 0; q < 2; q++) {
                int row = lr0 + q * 64;
                cp16(tb + (uint32_t)(row * PADR + lc) * 2,
                     base + (size_t)row * K + lc);
            }
        }
    };

    load_stage(0, 0);
    CP_COMMIT();
    load_stage(1, 1);
    CP_COMMIT();

    int s = 0;
    for (int it = 0; it < NIT; it++) {
        CP_WAIT(1);
        __syncthreads();
        if (it + 2 < NIT) {
            int s2 = s + 2; if (s2 >= 3) s2 -= 3;
            load_stage(it + 2, s2);
            CP_COMMIT();
        }

        uint32_t sA = smb + s * STAGE_B;
        uint32_t sB = sA + TILE_B;

        #pragma unroll
        for (int kk = 0; kk < 32; kk += 16) {
            uint32_t ah[4][4], bw[4][2];
            int arow = lane & 15;
            int acol = kk + ((lane >> 4) << 3);
            #pragma unroll
            for (int i = 0; i < 4; i++) {
                uint32_t off = (uint32_t)((wm * 64 + i * 16 + arow) * PADR + acol) * 2;
                ldm_x4(ah[i], sA + off);
            }
            int brow = lane & 7;
            int bcol = kk + ((lane >> 3) & 1) * 8;
            #pragma unroll
            for (int j = 0; j < 4; j++) {
                uint32_t off = (uint32_t)((wn * 32 + j * 8 + brow) * PADR + bcol) * 2;
                ldm_x2(bw[j], sB + off);
            }
            #pragma unroll
            for (int i = 0; i < 4; i++)
                #pragma unroll
                for (int j = 0; j < 4; j++)
                    mma_f16(acc[i][j], ah[i], bw[j]);
        }
        if (++s >= 3) s = 0;
    }

    #pragma unroll
    for (int i = 0; i < 4; i++) {
        #pragma unroll
        for (int j = 0; j < 4; j++) {
            int mb = m0 + wm * 64 + i * 16 + (lane >> 2);
            int nb = n0 + wn * 32 + j * 8 + (lane & 3) * 2;
            #pragma unroll
            for (int half = 0; half < 2; half++) {
                int m = mb + half * 8;
                float v0 = acc[i][j][half * 2 + 0];
                float v1 = acc[i][j][half * 2 + 1];
                if (bias) { v0 += bias[nb]; v1 += bias[nb + 1]; }
                if (gelu) {
                    v0 = 0.5f * v0 * (1.0f + erff(v0 * 0.70710678118654752f));
                    v1 = 0.5f * v1 * (1.0f + erff(v1 * 0.70710678118654752f));
                }
                size_t gi = (size_t)m * N + nb;
                if (res) {
                    float2 r2 = *(const float2*)(res + gi);
                    v0 += r2.x; v1 += r2.y;
                }
                if (outF) {
                    float2 o2 = make_float2(v0, v1);
                    *(float2*)(outF + gi) = o2;
                }
                if (outH) {
                    __half2 hh = __floats2half2_rn(v0, v1);
                    *(__half2*)(outH + gi) = hh;
                }
            }
        }
    }
}

// --------------------------- flash attention (fp16) -------------------------
#define FA_PAD 72
#define FS_Q  0u
#define FS_K  18432u            // 2 stages x 9216
#define FS_V  36864u            // 2 stages x 9216
#define FS_M  55296u            // 2 stages x 8192
#define FA_SMEM 71680u

__global__ void __launch_bounds__(256, 2) flash_attn(
    const __half* __restrict__ Qsrc, const __half* __restrict__ Ksrc,
    const __half* __restrict__ Vsrc,
    size_t qBatch, size_t kvBatch, int qStride, int kvStride,
    const unsigned char* __restrict__ maskp,
    __half* __restrict__ Oh)
{
    extern __shared__ char smem[];
    uint32_t smb = smem_u32(smem);
    int tid = threadIdx.x;
    int wid = tid >> 5, lane = tid & 31;
    int wq = wid << 4;
    int bh = blockIdx.y;
    int b = bh / Hh, h = bh % Hh;
    int qrow0 = blockIdx.x * 128;

    const __half* Qb = Qsrc + (size_t)b * qBatch + h * HD;
    const __half* Kb = Ksrc + (size_t)b * kvBatch + h * HD;
    const __half* Vb = Vsrc + (size_t)b * kvBatch + h * HD;

    auto load_kv = [&](int t, int s) {
        #pragma unroll
        for (int j2 = 0; j2 < 2; j2++) {
            int idx = tid + j2 * 256;
            int r = idx >> 3, c = (idx & 7) << 3;
            cp16(smb + FS_K + s * 9216u + (uint32_t)(r * FA_PAD + c) * 2,
                 Kb + (size_t)(t * 64 + r) * kvStride + c);
            cp16(smb + FS_V + s * 9216u + (uint32_t)(r * FA_PAD + c) * 2,
                 Vb + (size_t)(t * 64 + r) * kvStride + c);
        }
        if (maskp) {
            #pragma unroll
            for (int j2 = 0; j2 < 2; j2++) {
                int idx = tid + j2 * 256;
                int r = idx >> 2, c = (idx & 3) << 4;
                cp16(smb + FS_M + s * 8192u + (uint32_t)(r * 64 + c),
                     maskp + (size_t)(qrow0 + r) * NKk + t * 64 + c);
            }
        }
    };

    #pragma unroll
    for (int j4 = 0; j4 < 4; j4++) {
        int idx = tid + j4 * 256;
        int r = idx >> 3, c = (idx & 7) << 3;
        cp16(smb + FS_Q + (uint32_t)(r * FA_PAD + c) * 2,
             Qb + (size_t)(qrow0 + r) * qStride + c);
    }
    load_kv(0, 0);
    CP_COMMIT();

    uint32_t Aq[4][4];
    float O[8][4];
    #pragma unroll
    for (int j = 0; j < 8; j++)
        #pragma unroll
        for (int e = 0; e < 4; e++) O[j][e] = 0.f;
    float m0 = -1e30f, m1 = -1e30f, l0 = 0.f, l1 = 0.f;

    int r0l = wq + (lane >> 2);
    int cb2 = (lane & 3) * 2;

    for (int t = 0; t < 16; t++) {
        int s = t & 1;
        if (t + 1 < 16) {
            load_kv(t + 1, s ^ 1);
            CP_COMMIT();
            CP_WAIT(1);
        } else {
            CP_WAIT(0);
        }
        __syncthreads();

        if (t == 0) {
            #pragma unroll
            for (int kc = 0; kc < 4; kc++) {
                uint32_t off = (uint32_t)((wq + (lane & 15)) * FA_PAD
                               + kc * 16 + ((lane >> 4) << 3)) * 2;
                ldm_x4(Aq[kc], smb + FS_Q + off);
            }
        }

        float S[8][4];
        #pragma unroll
        for (int j = 0; j < 8; j++)
            #pragma unroll
            for (int e = 0; e < 4; e++) S[j][e] = 0.f;
        uint32_t sK = smb + FS_K + s * 9216u;
        #pragma unroll
        for (int kc = 0; kc < 4; kc++) {
            #pragma unroll
            for (int j = 0; j < 8; j++) {
                uint32_t bk[2];
                uint32_t off = (uint32_t)((8 * j + (lane & 7)) * FA_PAD
                               + 16 * kc + ((lane >> 3) & 1) * 8) * 2;
                ldm_x2(bk, sK + off);
                mma_f16(S[j], Aq[kc], bk);
            }
        }

        const unsigned char* sM = (const unsigned char*)(smem + FS_M + s * 8192u);
        #pragma unroll
        for (int j = 0; j < 8; j++) {
            S[j][0] *= SCALE; S[j][1] *= SCALE;
            S[j][2] *= SCALE; S[j][3] *= SCALE;
            if (maskp) {
                int col = 8 * j + cb2;
                unsigned short mw0 = *(const unsigned short*)(sM + r0l * 64 + col);
                unsigned short mw1 = *(const unsigned short*)(sM + (r0l + 8) * 64 + col);
                if (!(mw0 & 0xFF))   S[j][0] = -1e9f;
                if (!(mw0 >> 8))     S[j][1] = -1e9f;
                if (!(mw1 & 0xFF))   S[j][2] = -1e9f;
                if (!(mw1 >> 8))     S[j][3] = -1e9f;
            }
        }

        float mx0 = -1e30f, mx1 = -1e30f;
        #pragma unroll
        for (int j = 0; j < 8; j++) {
            mx0 = fmaxf(mx0, fmaxf(S[j][0], S[j][1]));
            mx1 = fmaxf(mx1, fmaxf(S[j][2], S[j][3]));
        }
        mx0 = fmaxf(mx0, __shfl_xor_sync(0xffffffffu, mx0, 1));
        mx0 = fmaxf(mx0, __shfl_xor_sync(0xffffffffu, mx0, 2));
        mx1 = fmaxf(mx1, __shfl_xor_sync(0xffffffffu, mx1, 1));
        mx1 = fmaxf(mx1, __shfl_xor_sync(0xffffffffu, mx1, 2));
        float mn0 = fmaxf(m0, mx0), mn1 = fmaxf(m1, mx1);
        float a0 = __expf(m0 - mn0), a1 = __expf(m1 - mn1);
        float sum0 = 0.f, sum1 = 0.f;
        #pragma unroll
        for (int j = 0; j < 8; j++) {
            S[j][0] = __expf(S[j][0] - mn0); sum0 += S[j][0];
            S[j][1] = __expf(S[j][1] - mn0); sum0 += S[j][1];
            S[j][2] = __expf(S[j][2] - mn1); sum1 += S[j][2];
            S[j][3] = __expf(S[j][3] - mn1); sum1 += S[j][3];
        }
        l0 = l0 * a0 + sum0;
        l1 = l1 * a1 + sum1;
        m0 = mn0; m1 = mn1;
        #pragma unroll
        for (int j = 0; j < 8; j++) {
            O[j][0] *= a0; O[j][1] *= a0;
            O[j][2] *= a1; O[j][3] *= a1;
        }

        uint32_t sV = smb + FS_V + s * 9216u;
        #pragma unroll
        for (int kc = 0; kc < 4; kc++) {
            uint32_t Ap[4];
            Ap[0] = packh(S[2 * kc][0],     S[2 * kc][1]);
            Ap[1] = packh(S[2 * kc][2],     S[2 * kc][3]);
            Ap[2] = packh(S[2 * kc + 1][0], S[2 * kc + 1][1]);
            Ap[3] = packh(S[2 * kc + 1][2], S[2 * kc + 1][3]);
            #pragma unroll
            for (int j = 0; j < 8; j++) {
                uint32_t bv[2];
                uint32_t off = (uint32_t)((16 * kc + (lane & 15)) * FA_PAD + 8 * j) * 2;
                ldm_x2t(bv, sV + off);
                mma_f16(O[j], Ap, bv);
            }
        }
        __syncthreads();
    }

    l0 += __shfl_xor_sync(0xffffffffu, l0, 1);
    l0 += __shfl_xor_sync(0xffffffffu, l0, 2);
    l1 += __shfl_xor_sync(0xffffffffu, l1, 1);
    l1 += __shfl_xor_sync(0xffffffffu, l1, 2);
    float inv0 = 1.f / l0, inv1 = 1.f / l1;
    int grow0 = qrow0 + r0l;
    size_t obase = (size_t)b * NQ * Cc + (size_t)h * HD;
    #pragma unroll
    for (int j = 0; j < 8; j++) {
        int col = 8 * j + cb2;
        size_t gi0 = obase + (size_t)grow0 * Cc + col;
        *(__half2*)(Oh + gi0) = __floats2half2_rn(O[j][0] * inv0, O[j][1] * inv0);
        size_t gi1 = obase + (size_t)(grow0 + 8) * Cc + col;
        *(__half2*)(Oh + gi1) = __floats2half2_rn(O[j][2] * inv1, O[j][3] * inv1);
    }
}

// ------------------------------ copy (y) -----------------------------------
__global__ void copy4_kernel(const float4* __restrict__ src, float4* __restrict__ dst, int n4)
{
    int i = blockIdx.x * blockDim.x + threadIdx.x;
    if (i < n4) dst[i] = src[i];
}

// ----------------------------- launch --------------------------------------
extern "C" void kernel_launch(void* const* d_in, const int* in_sizes, int n_in,
                              void* d_out, int out_size)
{
    const float* x        = (const float*)d_in[0];
    const float* y        = (const float*)d_in[1];
    const void*  mask_raw = d_in[4];
    const float* qkv_w    = (const float*)d_in[5];
    const float* aproj_w  = (const float*)d_in[6];
    const float* aproj_b  = (const float*)d_in[7];
    const float* q_w      = (const float*)d_in[8];
    const float* k_w      = (const float*)d_in[9];
    const float* v_w      = (const float*)d_in[10];
    const float* cproj_w  = (const float*)d_in[11];
    const float* cproj_b  = (const float*)d_in[12];
    const float* fc1_w    = (const float*)d_in[13];
    const float* fc1_b    = (const float*)d_in[14];
    const float* fc2_w    = (const float*)d_in[15];
    const float* fc2_b    = (const float*)d_in[16];
    const float* ln1_g    = (const float*)d_in[17];
    const float* ln1_b    = (const float*)d_in[18];
    const float* ln2_g    = (const float*)d_in[19];
    const float* ln2_b    = (const float*)d_in[20];
    const float* ln3_g    = (const float*)d_in[21];
    const float* ln3_b    = (const float*)d_in[22];
    const float* lny_g    = (const float*)d_in[23];
    const float* lny_b    = (const float*)d_in[24];
    float* out = (float*)d_out;

    float *p_x1, *p_x2;
    __half *p_qkvh, *p_qh, *p_kvh, *p_ln, *p_yln, *p_ao, *p_h1, *p_w;
    unsigned char* p_mask;
    cudaGetSymbolAddress((void**)&p_x1,  g_x1);
    cudaGetSymbolAddress((void**)&p_x2,  g_x2);
    cudaGetSymbolAddress((void**)&p_qkvh, g_qkvh);
    cudaGetSymbolAddress((void**)&p_qh,  g_qh);
    cudaGetSymbolAddress((void**)&p_kvh, g_kvh);
    cudaGetSymbolAddress((void**)&p_ln,  g_ln);
    cudaGetSymbolAddress((void**)&p_yln, g_yln);
    cudaGetSymbolAddress((void**)&p_ao,  g_ao);
    cudaGetSymbolAddress((void**)&p_h1,  g_h1);
    cudaGetSymbolAddress((void**)&p_w,   g_w);
    cudaGetSymbolAddress((void**)&p_mask, g_mask);

    cudaFuncSetAttribute(gemm_tc, cudaFuncAttributeMaxDynamicSharedMemorySize, GSM_TOTAL);
    cudaFuncSetAttribute(flash_attn, cudaFuncAttributeMaxDynamicSharedMemorySize, FA_SMEM);

    // side stream + events, created once (infra only; captured work identical
    // on every call)
    static cudaStream_t s1 = nullptr;
    static cudaEvent_t evFork = nullptr, evKV = nullptr;
    if (!s1) {
        cudaStreamCreateWithFlags(&s1, cudaStreamNonBlocking);
        cudaEventCreateWithFlags(&evFork, cudaEventDisableTiming);
        cudaEventCreateWithFlags(&evKV, cudaEventDisableTiming);
    }

    dim3 t256(256);
    dim3 gFlash(NQ / 128, Bb * Hh);

    // ---- stream 0: weight conversion first (y-branch KV GEMM needs it) ----
    wconvert_all<<<(W_TOT + 255) / 256, t256>>>(
        qkv_w, aproj_w, q_w, k_w, v_w, cproj_w, fc1_w, fc2_w);
    cudaEventRecord(evFork, 0);
    cudaStreamWaitEvent(s1, evFork, 0);

    // ---- stream s1: independent y-branch + mask ----
    mask_detect<<<1, 256, 0, s1>>>((const unsigned int*)mask_raw);
    mask_decode<<<(NQ * NKk + 255) / 256, t256, 0, s1>>>(mask_raw);
    ln_kernel<<<MROWS, t256, 0, s1>>>(y, lny_g, lny_b, p_yln);
    gemm_tc<<<dim3(2 * Cc / 128, MROWS / 128), t256, GSM_TOTAL, s1>>>(
        p_yln, p_w + W_K, Cc, 2 * Cc,
        nullptr, nullptr, 0, nullptr, p_kvh);
    {
        int n4 = (MROWS * Cc) / 4;
        copy4_kernel<<<(n4 + 255) / 256, t256, 0, s1>>>((const float4*)y,
            (float4*)(out + (size_t)MROWS * Cc), n4);
    }
    cudaEventRecord(evKV, s1);

    // ---- stream 0: self-attention chain ----
    ln_kernel<<<MROWS, t256>>>(x, ln1_g, ln1_b, p_ln);
    gemm_tc<<<dim3(3 * Cc / 128, MROWS / 128), t256, GSM_TOTAL>>>(
        p_ln, p_w + W_QKV, Cc, 3 * Cc,
        nullptr, nullptr, 0, nullptr, p_qkvh);
    flash_attn<<<gFlash, t256, FA_SMEM>>>(
        p_qkvh, p_qkvh + Cc, p_qkvh + 2 * Cc,
        (size_t)NQ * 3 * Cc, (size_t)NQ * 3 * Cc, 3 * Cc, 3 * Cc,
        nullptr, p_ao);
    gemm_tc<<<dim3(Cc / 128, MROWS / 128), t256, GSM_TOTAL>>>(
        p_ao, p_w + W_APROJ, Cc, Cc,
        aproj_b, x, 0, p_x1, nullptr);

    // ---- cross attention (join with y-branch before flash) ----
    ln_kernel<<<MROWS, t256>>>(p_x1, ln2_g, ln2_b, p_ln);
    gemm_tc<<<dim3(Cc / 128, MROWS / 128), t256, GSM_TOTAL>>>(
        p_ln, p_w + W_Q, Cc, Cc,
        nullptr, nullptr, 0, nullptr, p_qh);
    cudaStreamWaitEvent(0, evKV, 0);
    flash_attn<<<gFlash, t256, FA_SMEM>>>(
        p_qh, p_kvh, p_kvh + Cc,
        (size_t)NQ * Cc, (size_t)NKk * 2 * Cc, Cc, 2 * Cc,
        p_mask, p_ao);
    gemm_tc<<<dim3(Cc / 128, MROWS / 128), t256, GSM_TOTAL>>>(
        p_ao, p_w + W_CPROJ, Cc, Cc,
        cproj_b, p_x1, 0, p_x2, nullptr);

    // ---- MLP ----
    ln_kernel<<<MROWS, t256>>>(p_x2, ln3_g, ln3_b, p_ln);
    gemm_tc<<<dim3(HID / 128, MROWS / 128), t256, GSM_TOTAL>>>(
        p_ln, p_w + W_FC1, Cc, HID,
        fc1_b, nullptr, 1, nullptr, p_h1);
    gemm_tc<<<dim3(Cc / 128, MROWS / 128), t256, GSM_TOTAL>>>(
        p_h1, p_w + W_FC2, HID, Cc,
        fc2_b, p_x2, 0, out, nullptr);
}